// round 4
// baseline (speedup 1.0000x reference)
#include <cuda_runtime.h>
#include <cuda_bf16.h>
#include <cstdint>

#define Bc 2
#define Lc 2048
#define Hc 16
#define BHc 32
#define BM 128
#define NTILE 16
#define NCH 16
#define TILE_B 65536           // packed tile bytes: Khi|Klo|Vhi|Vlo, 16KB each

// ---------------- device scratch ----------------
__device__ float g_csum[BHc * NCH * 64];                         // per-tile V sums -> excl. suffix
__device__ unsigned char g_KV[(size_t)BHc * NTILE * TILE_B];     // pre-swizzled packed KV (32MB)

// ---------------- helpers ----------------
__device__ __forceinline__ uint32_t smem_u32(const void* p) {
    uint32_t a;
    asm("{ .reg .u64 t; cvta.to.shared.u64 t, %1; cvt.u32.u64 %0, t; }" : "=r"(a) : "l"(p));
    return a;
}
__device__ __forceinline__ float ex2f(float x) {
    float y; asm("ex2.approx.f32 %0, %1;" : "=f"(y) : "f"(x)); return y;
}
__device__ __forceinline__ void split2(float a, float b, uint32_t& hi, uint32_t& lo) {
    __nv_bfloat16 ha = __float2bfloat16(a), hb = __float2bfloat16(b);
    float ra = a - __bfloat162float(ha), rb = b - __bfloat162float(hb);
    __nv_bfloat162 H = __halves2bfloat162(ha, hb);
    __nv_bfloat162 L = __halves2bfloat162(__float2bfloat16(ra), __float2bfloat16(rb));
    hi = *reinterpret_cast<uint32_t*>(&H);
    lo = *reinterpret_cast<uint32_t*>(&L);
}
__device__ __forceinline__ void mma16816(float* c, const uint32_t* a, uint32_t b0, uint32_t b1) {
    asm volatile("mma.sync.aligned.m16n8k16.row.col.f32.bf16.bf16.f32 "
        "{%0,%1,%2,%3}, {%4,%5,%6,%7}, {%8,%9}, {%0,%1,%2,%3};"
        : "+f"(c[0]), "+f"(c[1]), "+f"(c[2]), "+f"(c[3])
        : "r"(a[0]), "r"(a[1]), "r"(a[2]), "r"(a[3]), "r"(b0), "r"(b1));
}
__device__ __forceinline__ void ldsm4(uint32_t addr, uint32_t* r) {
    asm volatile("ldmatrix.sync.aligned.m8n8.x4.shared.b16 {%0,%1,%2,%3}, [%4];"
        : "=r"(r[0]), "=r"(r[1]), "=r"(r[2]), "=r"(r[3]) : "r"(addr));
}
__device__ __forceinline__ void ldsm4t(uint32_t addr, uint32_t* r) {
    asm volatile("ldmatrix.sync.aligned.m8n8.x4.trans.shared.b16 {%0,%1,%2,%3}, [%4];"
        : "=r"(r[0]), "=r"(r[1]), "=r"(r[2]), "=r"(r[3]) : "r"(addr));
}
__device__ __forceinline__ void bulk_ld(uint32_t dst, const void* src, uint32_t bytes, uint32_t mbar) {
    asm volatile("cp.async.bulk.shared::cluster.global.mbarrier::complete_tx::bytes [%0], [%1], %2, [%3];"
        :: "r"(dst), "l"(src), "r"(bytes), "r"(mbar) : "memory");
}
#define MBAR_INIT(addr, cnt) \
    asm volatile("mbarrier.init.shared.b64 [%0], %1;" :: "r"((uint32_t)(addr)), "r"((uint32_t)(cnt)) : "memory")
#define MBAR_EXPECT_TX(addr, tx) \
    asm volatile("mbarrier.arrive.expect_tx.shared.b64 _, [%0], %1;" :: "r"((uint32_t)(addr)), "r"((uint32_t)(tx)) : "memory")
#define MBAR_WAIT(addr, par) do { \
    uint32_t _m = (uint32_t)(addr); uint32_t _p = (uint32_t)(par); uint32_t _d; \
    asm volatile("{ .reg .pred p; mbarrier.try_wait.parity.acquire.cta.shared::cta.b64 p, [%1], %2; selp.b32 %0,1,0,p; }" \
        : "=r"(_d) : "r"(_m), "r"(_p) : "memory"); \
    if (!_d) { \
        asm volatile("{ .reg .pred P1; WL_%=: mbarrier.try_wait.parity.acquire.cta.shared::cta.b64 P1, [%0], %1, 0x989680; @P1 bra.uni WD_%=; bra.uni WL_%=; WD_%=: }" \
            :: "r"(_m), "r"(_p) : "memory"); \
    } } while (0)

// ---------------- preprocessing ----------------

// fp32 K,V -> bf16 hi/lo, packed + XOR-swizzled, tile-contiguous [bh][t][arr][s][row128B]
__global__ void convert_kv(const float* __restrict__ K, const float* __restrict__ V) {
    uint32_t n = blockIdx.x * 256 + threadIdx.x;     // 524288 threads
    int ch = n & 7;
    int s  = (n >> 3) & 2047;
    int bh = n >> 14;
    int b = bh >> 4, h = bh & 15;
    int t = s >> 7, sr = s & 127;

    size_t src = (((size_t)b * Lc + s) * Hc + h) * 64 + ch * 8;
    size_t tb = ((size_t)(bh * NTILE + t)) * TILE_B;
    uint32_t roff = (uint32_t)sr * 128 + (((uint32_t)ch * 16) ^ (((uint32_t)sr & 7) << 4));

    float4 k0 = *(const float4*)(K + src), k1 = *(const float4*)(K + src + 4);
    float4 v0 = *(const float4*)(V + src), v1 = *(const float4*)(V + src + 4);

    uint4 khi, klo, vhi, vlo;
    split2(k0.x, k0.y, khi.x, klo.x); split2(k0.z, k0.w, khi.y, klo.y);
    split2(k1.x, k1.y, khi.z, klo.z); split2(k1.z, k1.w, khi.w, klo.w);
    split2(v0.x, v0.y, vhi.x, vlo.x); split2(v0.z, v0.w, vhi.y, vlo.y);
    split2(v1.x, v1.y, vhi.z, vlo.z); split2(v1.z, v1.w, vhi.w, vlo.w);

    *(uint4*)(g_KV + tb +     0 + roff) = khi;
    *(uint4*)(g_KV + tb + 16384 + roff) = klo;
    *(uint4*)(g_KV + tb + 32768 + roff) = vhi;
    *(uint4*)(g_KV + tb + 49152 + roff) = vlo;
}

// per-tile V column sums
__global__ void scan_chunks(const float* __restrict__ V) {
    int c = blockIdx.x, bh = blockIdx.y;
    int d = threadIdx.x & 63, rg = threadIdx.x >> 6;
    int b = bh >> 4, h = bh & 15;
    float s = 0.f;
    #pragma unroll 8
    for (int r = rg * 32; r < rg * 32 + 32; ++r)
        s += V[(((size_t)b * Lc + c * BM + r) * Hc + h) * 64 + d];
    __shared__ float red[256];
    red[threadIdx.x] = s;
    __syncthreads();
    if (threadIdx.x < 64)
        g_csum[(bh * NCH + c) * 64 + d] = red[d] + red[64 + d] + red[128 + d] + red[192 + d];
}

// in-place exclusive suffix of tile sums
__global__ void scan_offsets() {
    int i = blockIdx.x * 256 + threadIdx.x;          // 2048 columns
    int bh = i >> 6, d = i & 63;
    float v[NCH];
    #pragma unroll
    for (int c = 0; c < NCH; ++c) v[c] = g_csum[(bh * NCH + c) * 64 + d];
    float run = 0.f;
    #pragma unroll
    for (int c = NCH - 1; c >= 0; --c) {
        g_csum[(bh * NCH + c) * 64 + d] = run;
        run += v[c];
    }
}

// ---------------- main attention kernel ----------------
#define QSCALE 0.18033688011112042f   // 0.125 * log2(e)
#define SM_MB0 (2 * TILE_B)
#define SM_MB1 (2 * TILE_B + 8)
#define SM_TOTAL (2 * TILE_B + 128)

extern __shared__ __align__(1024) char dynsm[];

__global__ void __launch_bounds__(256) attn_mma(const float* __restrict__ Q,
                                                float* __restrict__ O) {
    const uint32_t sm = smem_u32(dynsm);
    const int tid = threadIdx.x;
    const int w = tid >> 5, lane = tid & 31;
    const int g = lane >> 2, quad = lane & 3;
    const int bh = blockIdx.y, b = bh >> 4, h = bh & 15;
    const int mtile = (NTILE - 1) - (int)blockIdx.x;   // heavy tiles first

    if (tid == 0) { MBAR_INIT(sm + SM_MB0, 1); MBAR_INIT(sm + SM_MB1, 1); }

    // per-lane ldmatrix geometry (XOR-swizzled, 128B rows)
    const int ks_row = (lane & 7) + ((lane >> 4) << 3);
    const uint32_t k_col = ((uint32_t)((lane >> 3) & 1)) * 16;
    const int vs_row = (lane & 7) + (((lane >> 3) & 1) << 3);
    const uint32_t v_col = ((uint32_t)(lane >> 4)) << 4;
    const uint32_t xo = ((uint32_t)(lane & 7)) << 4;

    // ---- Q fragments (hi/lo split, scale folded in) ----
    uint32_t Qh[4][4], Ql[4][4];
    {
        const float* qb = Q + (((size_t)b * Lc + (size_t)mtile * BM + w * 16) * Hc + h) * 64;
        #pragma unroll
        for (int kc = 0; kc < 4; ++kc) {
            int e0 = kc * 16 + quad * 2;
            float2 v00 = *(const float2*)(qb + (size_t)g * 1024 + e0);
            float2 v10 = *(const float2*)(qb + (size_t)(g + 8) * 1024 + e0);
            float2 v01 = *(const float2*)(qb + (size_t)g * 1024 + e0 + 8);
            float2 v11 = *(const float2*)(qb + (size_t)(g + 8) * 1024 + e0 + 8);
            split2(v00.x * QSCALE, v00.y * QSCALE, Qh[kc][0], Ql[kc][0]);
            split2(v10.x * QSCALE, v10.y * QSCALE, Qh[kc][1], Ql[kc][1]);
            split2(v01.x * QSCALE, v01.y * QSCALE, Qh[kc][2], Ql[kc][2]);
            split2(v11.x * QSCALE, v11.y * QSCALE, Qh[kc][3], Ql[kc][3]);
        }
    }
    __syncthreads();   // mbarrier init visible

    // prologue: issue tiles 0 and 1
    const unsigned char* kvbase = g_KV + (size_t)bh * NTILE * TILE_B;
    if (tid == 0) {
        MBAR_EXPECT_TX(sm + SM_MB0, TILE_B);
        bulk_ld(sm, kvbase, TILE_B, sm + SM_MB0);
        if (mtile >= 1) {
            MBAR_EXPECT_TX(sm + SM_MB1, TILE_B);
            bulk_ld(sm + TILE_B, kvbase + TILE_B, TILE_B, sm + SM_MB1);
        }
    }

    float Oa[8][4];
    #pragma unroll
    for (int i = 0; i < 8; ++i)
        #pragma unroll
        for (int j = 0; j < 4; ++j) Oa[i][j] = 0.f;
    float den0 = 0.f, den1 = 0.f;

    #pragma unroll 1
    for (int t = 0; t <= mtile; ++t) {
        MBAR_WAIT(sm + ((t & 1) ? SM_MB1 : SM_MB0), (t >> 1) & 1);

        const uint32_t stg = sm + (uint32_t)(t & 1) * TILE_B;
        const uint32_t khi_b = stg, klo_b = stg + 16384;
        const uint32_t vhi_b = stg + 32768, vlo_b = stg + 49152;

        // ---- S = Q Kt (3-way bf16 split) ----
        float S[16][4];
        #pragma unroll
        for (int i = 0; i < 16; ++i)
            #pragma unroll
            for (int j = 0; j < 4; ++j) S[i][j] = 0.f;

        #pragma unroll
        for (int kc = 0; kc < 4; ++kc) {
            #pragma unroll
            for (int nbp = 0; nbp < 8; ++nbp) {
                uint32_t off = (uint32_t)(nbp * 16 + ks_row) * 128
                             + (((uint32_t)kc * 32 + k_col) ^ xo);
                uint32_t kb[4], kl4[4];
                ldsm4(khi_b + off, kb);
                ldsm4(klo_b + off, kl4);
                mma16816(S[2*nbp],   Qh[kc], kb[0], kb[1]);
                mma16816(S[2*nbp+1], Qh[kc], kb[2], kb[3]);
                mma16816(S[2*nbp],   Ql[kc], kb[0], kb[1]);
                mma16816(S[2*nbp+1], Ql[kc], kb[2], kb[3]);
                mma16816(S[2*nbp],   Qh[kc], kl4[0], kl4[1]);
                mma16816(S[2*nbp+1], Qh[kc], kl4[2], kl4[3]);
            }
        }

        // ---- exp; masked (future) slots contribute exp(0)=1 (reference semantics) ----
        const int lim0 = (t == mtile) ? (w * 16 + g) : 127;
        const int lim1 = (t == mtile) ? (w * 16 + g + 8) : 127;
        uint32_t Ph[8][4], Pl[8][4];
        #pragma unroll
        for (int nb = 0; nb < 16; ++nb) {
            int s0 = nb * 8 + quad * 2;
            float p0 = (s0     <= lim0) ? ex2f(S[nb][0]) : 1.f;
            float p1 = (s0 + 1 <= lim0) ? ex2f(S[nb][1]) : 1.f;
            float p2 = (s0     <= lim1) ? ex2f(S[nb][2]) : 1.f;
            float p3 = (s0 + 1 <= lim1) ? ex2f(S[nb][3]) : 1.f;
            den0 += p0 + p1;
            den1 += p2 + p3;
            split2(p0, p1, Ph[nb >> 1][(nb & 1) * 2],     Pl[nb >> 1][(nb & 1) * 2]);
            split2(p2, p3, Ph[nb >> 1][(nb & 1) * 2 + 1], Pl[nb >> 1][(nb & 1) * 2 + 1]);
        }

        // ---- O += P V (3-way bf16 split) ----
        #pragma unroll
        for (int kcs = 0; kcs < 8; ++kcs) {
            #pragma unroll
            for (int nbp = 0; nbp < 4; ++nbp) {
                uint32_t off = (uint32_t)(kcs * 16 + vs_row) * 128
                             + (((uint32_t)nbp * 32 + v_col) ^ xo);
                uint32_t vb[4], vl4[4];
                ldsm4t(vhi_b + off, vb);
                ldsm4t(vlo_b + off, vl4);
                mma16816(Oa[2*nbp],   Ph[kcs], vb[0], vb[1]);
                mma16816(Oa[2*nbp+1], Ph[kcs], vb[2], vb[3]);
                mma16816(Oa[2*nbp],   Pl[kcs], vb[0], vb[1]);
                mma16816(Oa[2*nbp+1], Pl[kcs], vb[2], vb[3]);
                mma16816(Oa[2*nbp],   Ph[kcs], vl4[0], vl4[1]);
                mma16816(Oa[2*nbp+1], Ph[kcs], vl4[2], vl4[3]);
            }
        }

        __syncthreads();   // all reads of stage t done before refill
        if (tid == 0 && t + 2 <= mtile) {
            uint32_t mb = sm + ((t & 1) ? SM_MB1 : SM_MB0);
            MBAR_EXPECT_TX(mb, TILE_B);
            bulk_ld(stg, kvbase + (size_t)(t + 2) * TILE_B, TILE_B, mb);
        }
    }

    // ---- epilogue ----
    den0 += __shfl_xor_sync(0xffffffffu, den0, 1);
    den0 += __shfl_xor_sync(0xffffffffu, den0, 2);
    den1 += __shfl_xor_sync(0xffffffffu, den1, 1);
    den1 += __shfl_xor_sync(0xffffffffu, den1, 2);

    const float corr = (float)(Lc - (mtile + 1) * BM);   // masked slots beyond this tile
    const float inv0 = 1.f / (den0 + corr);
    const float inv1 = 1.f / (den1 + corr);

    const int r0g = mtile * BM + w * 16 + g;
    const int r1g = r0g + 8;
    const size_t ob0 = (((size_t)b * Lc + r0g) * Hc + h) * 64;
    const size_t ob1 = (((size_t)b * Lc + r1g) * Hc + h) * 64;
    const float* sfx = &g_csum[(bh * NCH + mtile) * 64];

    #pragma unroll
    for (int nb = 0; nb < 8; ++nb) {
        int d0 = nb * 8 + quad * 2;
        float2 s2 = *(const float2*)(sfx + d0);
        float2 o0 = make_float2((Oa[nb][0] + s2.x) * inv0, (Oa[nb][1] + s2.y) * inv0);
        float2 o1 = make_float2((Oa[nb][2] + s2.x) * inv1, (Oa[nb][3] + s2.y) * inv1);
        *(float2*)&O[ob0 + d0] = o0;
        *(float2*)&O[ob1 + d0] = o1;
    }
}

// ---------------- launch ----------------
extern "C" void kernel_launch(void* const* d_in, const int* in_sizes, int n_in,
                              void* d_out, int out_size) {
    const float* Q = (const float*)d_in[0];
    const float* K = (const float*)d_in[1];
    const float* V = (const float*)d_in[2];
    float* O = (float*)d_out;

    convert_kv<<<2048, 256>>>(K, V);
    scan_chunks<<<dim3(NCH, BHc), 256>>>(V);
    scan_offsets<<<8, 256>>>();

    cudaFuncSetAttribute(attn_mma, cudaFuncAttributeMaxDynamicSharedMemorySize, SM_TOTAL);
    attn_mma<<<dim3(NTILE, BHc), 256, SM_TOTAL>>>(Q, O);
}

// round 5
// speedup vs baseline: 1.0588x; 1.0588x over previous
#include <cuda_runtime.h>
#include <cuda_bf16.h>
#include <cstdint>

#define Bc 2
#define Lc 2048
#define Hc 16
#define BHc 32
#define BM 128                 // q-rows per CTA
#define BN 64                  // s-rows per tile
#define NQT 16                 // q tiles
#define NST 32                 // s tiles
#define NCH 16
#define TILE_B 32768           // packed tile: Khi|Klo|Vhi|Vlo, 8KB each

// ---------------- device scratch ----------------
__device__ float g_csum[BHc * NCH * 64];                        // per-128-chunk V sums -> excl. suffix
__device__ unsigned char g_KV[(size_t)BHc * NST * TILE_B];      // pre-swizzled packed KV (32MB)

// ---------------- helpers ----------------
__device__ __forceinline__ uint32_t smem_u32(const void* p) {
    uint32_t a;
    asm("{ .reg .u64 t; cvta.to.shared.u64 t, %1; cvt.u32.u64 %0, t; }" : "=r"(a) : "l"(p));
    return a;
}
__device__ __forceinline__ float ex2f(float x) {
    float y; asm("ex2.approx.f32 %0, %1;" : "=f"(y) : "f"(x)); return y;
}
__device__ __forceinline__ void split2(float a, float b, uint32_t& hi, uint32_t& lo) {
    __nv_bfloat16 ha = __float2bfloat16(a), hb = __float2bfloat16(b);
    float ra = a - __bfloat162float(ha), rb = b - __bfloat162float(hb);
    __nv_bfloat162 H = __halves2bfloat162(ha, hb);
    __nv_bfloat162 L = __halves2bfloat162(__float2bfloat16(ra), __float2bfloat16(rb));
    hi = *reinterpret_cast<uint32_t*>(&H);
    lo = *reinterpret_cast<uint32_t*>(&L);
}
__device__ __forceinline__ void mma16816(float* c, const uint32_t* a, uint32_t b0, uint32_t b1) {
    asm volatile("mma.sync.aligned.m16n8k16.row.col.f32.bf16.bf16.f32 "
        "{%0,%1,%2,%3}, {%4,%5,%6,%7}, {%8,%9}, {%0,%1,%2,%3};"
        : "+f"(c[0]), "+f"(c[1]), "+f"(c[2]), "+f"(c[3])
        : "r"(a[0]), "r"(a[1]), "r"(a[2]), "r"(a[3]), "r"(b0), "r"(b1));
}
__device__ __forceinline__ void ldsm4(uint32_t addr, uint32_t* r) {
    asm volatile("ldmatrix.sync.aligned.m8n8.x4.shared.b16 {%0,%1,%2,%3}, [%4];"
        : "=r"(r[0]), "=r"(r[1]), "=r"(r[2]), "=r"(r[3]) : "r"(addr));
}
__device__ __forceinline__ void ldsm4t(uint32_t addr, uint32_t* r) {
    asm volatile("ldmatrix.sync.aligned.m8n8.x4.trans.shared.b16 {%0,%1,%2,%3}, [%4];"
        : "=r"(r[0]), "=r"(r[1]), "=r"(r[2]), "=r"(r[3]) : "r"(addr));
}
__device__ __forceinline__ void bulk_ld(uint32_t dst, const void* src, uint32_t bytes, uint32_t mbar) {
    asm volatile("cp.async.bulk.shared::cluster.global.mbarrier::complete_tx::bytes [%0], [%1], %2, [%3];"
        :: "r"(dst), "l"(src), "r"(bytes), "r"(mbar) : "memory");
}
#define MBAR_INIT(addr, cnt) \
    asm volatile("mbarrier.init.shared.b64 [%0], %1;" :: "r"((uint32_t)(addr)), "r"((uint32_t)(cnt)) : "memory")
#define MBAR_EXPECT_TX(addr, tx) \
    asm volatile("mbarrier.arrive.expect_tx.shared.b64 _, [%0], %1;" :: "r"((uint32_t)(addr)), "r"((uint32_t)(tx)) : "memory")
#define MBAR_WAIT(addr, par) do { \
    uint32_t _m = (uint32_t)(addr); uint32_t _p = (uint32_t)(par); uint32_t _d; \
    asm volatile("{ .reg .pred p; mbarrier.try_wait.parity.acquire.cta.shared::cta.b64 p, [%1], %2; selp.b32 %0,1,0,p; }" \
        : "=r"(_d) : "r"(_m), "r"(_p) : "memory"); \
    if (!_d) { \
        asm volatile("{ .reg .pred P1; WL_%=: mbarrier.try_wait.parity.acquire.cta.shared::cta.b64 P1, [%0], %1, 0x989680; @P1 bra.uni WD_%=; bra.uni WL_%=; WD_%=: }" \
            :: "r"(_m), "r"(_p) : "memory"); \
    } } while (0)

// ---------------- preprocessing ----------------

// fp32 K,V -> bf16 hi/lo, packed + XOR-swizzled, tile-contiguous [bh][t64][arr][sr][128B]
__global__ void convert_kv(const float* __restrict__ K, const float* __restrict__ V) {
    uint32_t n = blockIdx.x * 256 + threadIdx.x;     // 524288 threads
    int ch = n & 7;
    int s  = (n >> 3) & 2047;
    int bh = n >> 14;
    int b = bh >> 4, h = bh & 15;
    int t = s >> 6, sr = s & 63;

    size_t src = (((size_t)b * Lc + s) * Hc + h) * 64 + ch * 8;
    size_t tb = ((size_t)(bh * NST + t)) * TILE_B;
    uint32_t roff = (uint32_t)sr * 128 + (((uint32_t)ch * 16) ^ (((uint32_t)sr & 7) << 4));

    float4 k0 = *(const float4*)(K + src), k1 = *(const float4*)(K + src + 4);
    float4 v0 = *(const float4*)(V + src), v1 = *(const float4*)(V + src + 4);

    uint4 khi, klo, vhi, vlo;
    split2(k0.x, k0.y, khi.x, klo.x); split2(k0.z, k0.w, khi.y, klo.y);
    split2(k1.x, k1.y, khi.z, klo.z); split2(k1.z, k1.w, khi.w, klo.w);
    split2(v0.x, v0.y, vhi.x, vlo.x); split2(v0.z, v0.w, vhi.y, vlo.y);
    split2(v1.x, v1.y, vhi.z, vlo.z); split2(v1.z, v1.w, vhi.w, vlo.w);

    *(uint4*)(g_KV + tb +     0 + roff) = khi;
    *(uint4*)(g_KV + tb +  8192 + roff) = klo;
    *(uint4*)(g_KV + tb + 16384 + roff) = vhi;
    *(uint4*)(g_KV + tb + 24576 + roff) = vlo;
}

// per-128-chunk V column sums
__global__ void scan_chunks(const float* __restrict__ V) {
    int c = blockIdx.x, bh = blockIdx.y;
    int d = threadIdx.x & 63, rg = threadIdx.x >> 6;
    int b = bh >> 4, h = bh & 15;
    float s = 0.f;
    #pragma unroll 8
    for (int r = rg * 32; r < rg * 32 + 32; ++r)
        s += V[(((size_t)b * Lc + c * BM + r) * Hc + h) * 64 + d];
    __shared__ float red[256];
    red[threadIdx.x] = s;
    __syncthreads();
    if (threadIdx.x < 64)
        g_csum[(bh * NCH + c) * 64 + d] = red[d] + red[64 + d] + red[128 + d] + red[192 + d];
}

// in-place exclusive suffix of chunk sums
__global__ void scan_offsets() {
    int i = blockIdx.x * 256 + threadIdx.x;          // 2048 columns
    int bh = i >> 6, d = i & 63;
    float v[NCH];
    #pragma unroll
    for (int c = 0; c < NCH; ++c) v[c] = g_csum[(bh * NCH + c) * 64 + d];
    float run = 0.f;
    #pragma unroll
    for (int c = NCH - 1; c >= 0; --c) {
        g_csum[(bh * NCH + c) * 64 + d] = run;
        run += v[c];
    }
}

// ---------------- main attention kernel ----------------
#define QSCALE 0.18033688011112042f   // 0.125 * log2(e)
#define SM_MB0 (2 * TILE_B)
#define SM_MB1 (2 * TILE_B + 8)
#define SM_TOTAL (2 * TILE_B + 128)   // 65664 -> 2 CTAs/SM

extern __shared__ __align__(1024) char dynsm[];

__global__ void __launch_bounds__(256, 2) attn_mma(const float* __restrict__ Q,
                                                   float* __restrict__ O) {
    const uint32_t sm = smem_u32(dynsm);
    const int tid = threadIdx.x;
    const int w = tid >> 5, lane = tid & 31;
    const int g = lane >> 2, quad = lane & 3;
    const int bh = blockIdx.y, b = bh >> 4, h = bh & 15;
    const int mtile = (NQT - 1) - (int)blockIdx.x;   // heavy q-tiles first
    const int tmax = 2 * mtile + 1;                  // s tiles 0..tmax

    if (tid == 0) { MBAR_INIT(sm + SM_MB0, 1); MBAR_INIT(sm + SM_MB1, 1); }

    // per-lane ldmatrix geometry (XOR-swizzled, 128B rows)
    const int ks_row = (lane & 7) + ((lane >> 4) << 3);
    const uint32_t k_col = ((uint32_t)((lane >> 3) & 1)) * 16;
    const int vs_row = (lane & 7) + (((lane >> 3) & 1) << 3);
    const uint32_t v_col = ((uint32_t)(lane >> 4)) << 4;
    const uint32_t xo = ((uint32_t)(lane & 7)) << 4;

    // ---- Q fragments (hi/lo split, scale folded in) ----
    uint32_t Qh[4][4], Ql[4][4];
    {
        const float* qb = Q + (((size_t)b * Lc + (size_t)mtile * BM + w * 16) * Hc + h) * 64;
        #pragma unroll
        for (int kc = 0; kc < 4; ++kc) {
            int e0 = kc * 16 + quad * 2;
            float2 v00 = *(const float2*)(qb + (size_t)g * 1024 + e0);
            float2 v10 = *(const float2*)(qb + (size_t)(g + 8) * 1024 + e0);
            float2 v01 = *(const float2*)(qb + (size_t)g * 1024 + e0 + 8);
            float2 v11 = *(const float2*)(qb + (size_t)(g + 8) * 1024 + e0 + 8);
            split2(v00.x * QSCALE, v00.y * QSCALE, Qh[kc][0], Ql[kc][0]);
            split2(v10.x * QSCALE, v10.y * QSCALE, Qh[kc][1], Ql[kc][1]);
            split2(v01.x * QSCALE, v01.y * QSCALE, Qh[kc][2], Ql[kc][2]);
            split2(v11.x * QSCALE, v11.y * QSCALE, Qh[kc][3], Ql[kc][3]);
        }
    }
    __syncthreads();   // mbarrier init visible

    // prologue: issue tiles 0 and 1 (tmax >= 1 always)
    const unsigned char* kvbase = g_KV + (size_t)bh * NST * TILE_B;
    if (tid == 0) {
        MBAR_EXPECT_TX(sm + SM_MB0, TILE_B);
        bulk_ld(sm, kvbase, TILE_B, sm + SM_MB0);
        MBAR_EXPECT_TX(sm + SM_MB1, TILE_B);
        bulk_ld(sm + TILE_B, kvbase + TILE_B, TILE_B, sm + SM_MB1);
    }

    float Oa[8][4];
    #pragma unroll
    for (int i = 0; i < 8; ++i)
        #pragma unroll
        for (int j = 0; j < 4; ++j) Oa[i][j] = 0.f;
    float den0 = 0.f, den1 = 0.f;

    const int rowA = w * 16 + g;        // in-q-tile row of C-frag rows {0,1}
    // global rows: mtile*128 + rowA, +8

    #pragma unroll 1
    for (int t = 0; t <= tmax; ++t) {
        MBAR_WAIT(sm + ((t & 1) ? SM_MB1 : SM_MB0), (t >> 1) & 1);

        const uint32_t stg = sm + (uint32_t)(t & 1) * TILE_B;
        const uint32_t khi_b = stg, klo_b = stg + 8192;
        const uint32_t vhi_b = stg + 16384, vlo_b = stg + 24576;

        // ---- S = Q Kt (3-way bf16 split) ----
        float S[8][4];
        #pragma unroll
        for (int i = 0; i < 8; ++i)
            #pragma unroll
            for (int j = 0; j < 4; ++j) S[i][j] = 0.f;

        #pragma unroll
        for (int kc = 0; kc < 4; ++kc) {
            #pragma unroll
            for (int nbp = 0; nbp < 4; ++nbp) {
                uint32_t off = (uint32_t)(nbp * 16 + ks_row) * 128
                             + (((uint32_t)kc * 32 + k_col) ^ xo);
                uint32_t kb[4], kl4[4];
                ldsm4(khi_b + off, kb);
                ldsm4(klo_b + off, kl4);
                mma16816(S[2*nbp],   Qh[kc], kb[0], kb[1]);
                mma16816(S[2*nbp+1], Qh[kc], kb[2], kb[3]);
                mma16816(S[2*nbp],   Ql[kc], kb[0], kb[1]);
                mma16816(S[2*nbp+1], Ql[kc], kb[2], kb[3]);
                mma16816(S[2*nbp],   Qh[kc], kl4[0], kl4[1]);
                mma16816(S[2*nbp+1], Qh[kc], kl4[2], kl4[3]);
            }
        }

        // ---- exp; masked (future) slots contribute exp(0)=1 (reference semantics) ----
        // in-tile col limit: s_local <= row_global - 64t
        const int lim0 = (mtile * BM + rowA) - (t << 6);
        const int lim1 = lim0 + 8;
        uint32_t Ph[4][4], Pl[4][4];
        #pragma unroll
        for (int nb = 0; nb < 8; ++nb) {
            int s0 = nb * 8 + quad * 2;
            float p0 = (s0     <= lim0) ? ex2f(S[nb][0]) : 1.f;
            float p1 = (s0 + 1 <= lim0) ? ex2f(S[nb][1]) : 1.f;
            float p2 = (s0     <= lim1) ? ex2f(S[nb][2]) : 1.f;
            float p3 = (s0 + 1 <= lim1) ? ex2f(S[nb][3]) : 1.f;
            den0 += p0 + p1;
            den1 += p2 + p3;
            split2(p0, p1, Ph[nb >> 1][(nb & 1) * 2],     Pl[nb >> 1][(nb & 1) * 2]);
            split2(p2, p3, Ph[nb >> 1][(nb & 1) * 2 + 1], Pl[nb >> 1][(nb & 1) * 2 + 1]);
        }

        // ---- O += P V (3-way bf16 split) ----
        #pragma unroll
        for (int kcs = 0; kcs < 4; ++kcs) {
            #pragma unroll
            for (int nbp = 0; nbp < 4; ++nbp) {
                uint32_t off = (uint32_t)(kcs * 16 + vs_row) * 128
                             + (((uint32_t)nbp * 32 + v_col) ^ xo);
                uint32_t vb[4], vl4[4];
                ldsm4t(vhi_b + off, vb);
                ldsm4t(vlo_b + off, vl4);
                mma16816(Oa[2*nbp],   Ph[kcs], vb[0], vb[1]);
                mma16816(Oa[2*nbp+1], Ph[kcs], vb[2], vb[3]);
                mma16816(Oa[2*nbp],   Pl[kcs], vb[0], vb[1]);
                mma16816(Oa[2*nbp+1], Pl[kcs], vb[2], vb[3]);
                mma16816(Oa[2*nbp],   Ph[kcs], vl4[0], vl4[1]);
                mma16816(Oa[2*nbp+1], Ph[kcs], vl4[2], vl4[3]);
            }
        }

        __syncthreads();   // all reads of stage (t&1) done before refill
        if (tid == 0 && t + 2 <= tmax) {
            uint32_t mb = sm + ((t & 1) ? SM_MB1 : SM_MB0);
            MBAR_EXPECT_TX(mb, TILE_B);
            bulk_ld(stg, kvbase + (size_t)(t + 2) * TILE_B, TILE_B, mb);
        }
    }

    // ---- epilogue ----
    den0 += __shfl_xor_sync(0xffffffffu, den0, 1);
    den0 += __shfl_xor_sync(0xffffffffu, den0, 2);
    den1 += __shfl_xor_sync(0xffffffffu, den1, 1);
    den1 += __shfl_xor_sync(0xffffffffu, den1, 2);

    const float corr = (float)(Lc - (mtile + 1) * BM);   // masked slots beyond processed tiles
    const float inv0 = 1.f / (den0 + corr);
    const float inv1 = 1.f / (den1 + corr);

    const int r0g = mtile * BM + rowA;
    const int r1g = r0g + 8;
    const size_t ob0 = (((size_t)b * Lc + r0g) * Hc + h) * 64;
    const size_t ob1 = (((size_t)b * Lc + r1g) * Hc + h) * 64;
    const float* sfx = &g_csum[(bh * NCH + mtile) * 64];

    #pragma unroll
    for (int nb = 0; nb < 8; ++nb) {
        int d0 = nb * 8 + quad * 2;
        float2 s2 = *(const float2*)(sfx + d0);
        float2 o0 = make_float2((Oa[nb][0] + s2.x) * inv0, (Oa[nb][1] + s2.y) * inv0);
        float2 o1 = make_float2((Oa[nb][2] + s2.x) * inv1, (Oa[nb][3] + s2.y) * inv1);
        *(float2*)&O[ob0 + d0] = o0;
        *(float2*)&O[ob1 + d0] = o1;
    }
}

// ---------------- launch ----------------
extern "C" void kernel_launch(void* const* d_in, const int* in_sizes, int n_in,
                              void* d_out, int out_size) {
    const float* Q = (const float*)d_in[0];
    const float* K = (const float*)d_in[1];
    const float* V = (const float*)d_in[2];
    float* O = (float*)d_out;

    convert_kv<<<2048, 256>>>(K, V);
    scan_chunks<<<dim3(NCH, BHc), 256>>>(V);
    scan_offsets<<<8, 256>>>();

    cudaFuncSetAttribute(attn_mma, cudaFuncAttributeMaxDynamicSharedMemorySize, SM_TOTAL);
    attn_mma<<<dim3(NQT, BHc), 256, SM_TOTAL>>>(Q, O);
}

// round 6
// speedup vs baseline: 1.1672x; 1.1024x over previous
#include <cuda_runtime.h>
#include <cuda_bf16.h>
#include <cstdint>

#define Bc 2
#define Lc 2048
#define Hc 16
#define BHc 32
#define BM 128                 // q-rows per CTA
#define BN 64                  // s-rows per tile
#define NQT 16                 // q tiles
#define NST 32                 // s tiles
#define NCH 16
#define TILE_B 32768           // packed tile: Khi|Klo|Vhi|Vlo, 8KB each

// ---------------- device scratch ----------------
__device__ float g_csum[BHc * NCH * 64];                        // per-128-chunk V sums -> excl. suffix
__device__ unsigned char g_KV[(size_t)BHc * NST * TILE_B];      // pre-swizzled packed KV (32MB)

// ---------------- helpers ----------------
__device__ __forceinline__ uint32_t smem_u32(const void* p) {
    uint32_t a;
    asm("{ .reg .u64 t; cvta.to.shared.u64 t, %1; cvt.u32.u64 %0, t; }" : "=r"(a) : "l"(p));
    return a;
}
__device__ __forceinline__ float ex2f(float x) {
    float y; asm("ex2.approx.f32 %0, %1;" : "=f"(y) : "f"(x)); return y;
}
// fast hi/lo bf16 split: 2 packed cvts + 2 bitops + 2 subs
__device__ __forceinline__ void split2(float a, float b, uint32_t& hi, uint32_t& lo) {
    uint32_t h;
    asm("cvt.rn.bf16x2.f32 %0, %1, %2;" : "=r"(h) : "f"(b), "f"(a));   // hi16=b, lo16=a
    float fa = __uint_as_float(h << 16);
    float fb = __uint_as_float(h & 0xFFFF0000u);
    float ra = a - fa, rb = b - fb;
    asm("cvt.rn.bf16x2.f32 %0, %1, %2;" : "=r"(lo) : "f"(rb), "f"(ra));
    hi = h;
}
__device__ __forceinline__ void mma16816(float* c, const uint32_t* a, uint32_t b0, uint32_t b1) {
    asm volatile("mma.sync.aligned.m16n8k16.row.col.f32.bf16.bf16.f32 "
        "{%0,%1,%2,%3}, {%4,%5,%6,%7}, {%8,%9}, {%0,%1,%2,%3};"
        : "+f"(c[0]), "+f"(c[1]), "+f"(c[2]), "+f"(c[3])
        : "r"(a[0]), "r"(a[1]), "r"(a[2]), "r"(a[3]), "r"(b0), "r"(b1));
}
__device__ __forceinline__ void ldsm4(uint32_t addr, uint32_t* r) {
    asm volatile("ldmatrix.sync.aligned.m8n8.x4.shared.b16 {%0,%1,%2,%3}, [%4];"
        : "=r"(r[0]), "=r"(r[1]), "=r"(r[2]), "=r"(r[3]) : "r"(addr));
}
__device__ __forceinline__ void ldsm4t(uint32_t addr, uint32_t* r) {
    asm volatile("ldmatrix.sync.aligned.m8n8.x4.trans.shared.b16 {%0,%1,%2,%3}, [%4];"
        : "=r"(r[0]), "=r"(r[1]), "=r"(r[2]), "=r"(r[3]) : "r"(addr));
}
__device__ __forceinline__ void bulk_ld(uint32_t dst, const void* src, uint32_t bytes, uint32_t mbar) {
    asm volatile("cp.async.bulk.shared::cluster.global.mbarrier::complete_tx::bytes [%0], [%1], %2, [%3];"
        :: "r"(dst), "l"(src), "r"(bytes), "r"(mbar) : "memory");
}
#define MBAR_INIT(addr, cnt) \
    asm volatile("mbarrier.init.shared.b64 [%0], %1;" :: "r"((uint32_t)(addr)), "r"((uint32_t)(cnt)) : "memory")
#define MBAR_EXPECT_TX(addr, tx) \
    asm volatile("mbarrier.arrive.expect_tx.shared.b64 _, [%0], %1;" :: "r"((uint32_t)(addr)), "r"((uint32_t)(tx)) : "memory")
#define MBAR_ARRIVE(addr) \
    asm volatile("mbarrier.arrive.shared.b64 _, [%0];" :: "r"((uint32_t)(addr)) : "memory")
#define MBAR_WAIT(addr, par) do { \
    uint32_t _m = (uint32_t)(addr); uint32_t _p = (uint32_t)(par); uint32_t _d; \
    asm volatile("{ .reg .pred p; mbarrier.try_wait.parity.acquire.cta.shared::cta.b64 p, [%1], %2; selp.b32 %0,1,0,p; }" \
        : "=r"(_d) : "r"(_m), "r"(_p) : "memory"); \
    if (!_d) { \
        asm volatile("{ .reg .pred P1; WL_%=: mbarrier.try_wait.parity.acquire.cta.shared::cta.b64 P1, [%0], %1, 0x989680; @P1 bra.uni WD_%=; bra.uni WL_%=; WD_%=: }" \
            :: "r"(_m), "r"(_p) : "memory"); \
    } } while (0)

// ---------------- preprocessing ----------------

// fp32 K,V -> bf16 hi/lo, packed + XOR-swizzled, tile-contiguous [bh][t64][arr][sr][128B]
__global__ void convert_kv(const float* __restrict__ K, const float* __restrict__ V) {
    uint32_t n = blockIdx.x * 256 + threadIdx.x;     // 524288 threads
    int ch = n & 7;
    int s  = (n >> 3) & 2047;
    int bh = n >> 14;
    int b = bh >> 4, h = bh & 15;
    int t = s >> 6, sr = s & 63;

    size_t src = (((size_t)b * Lc + s) * Hc + h) * 64 + ch * 8;
    size_t tb = ((size_t)(bh * NST + t)) * TILE_B;
    uint32_t roff = (uint32_t)sr * 128 + (((uint32_t)ch * 16) ^ (((uint32_t)sr & 7) << 4));

    float4 k0 = *(const float4*)(K + src), k1 = *(const float4*)(K + src + 4);
    float4 v0 = *(const float4*)(V + src), v1 = *(const float4*)(V + src + 4);

    uint4 khi, klo, vhi, vlo;
    split2(k0.x, k0.y, khi.x, klo.x); split2(k0.z, k0.w, khi.y, klo.y);
    split2(k1.x, k1.y, khi.z, klo.z); split2(k1.z, k1.w, khi.w, klo.w);
    split2(v0.x, v0.y, vhi.x, vlo.x); split2(v0.z, v0.w, vhi.y, vlo.y);
    split2(v1.x, v1.y, vhi.z, vlo.z); split2(v1.z, v1.w, vhi.w, vlo.w);

    *(uint4*)(g_KV + tb +     0 + roff) = khi;
    *(uint4*)(g_KV + tb +  8192 + roff) = klo;
    *(uint4*)(g_KV + tb + 16384 + roff) = vhi;
    *(uint4*)(g_KV + tb + 24576 + roff) = vlo;
}

// per-128-chunk V column sums
__global__ void scan_chunks(const float* __restrict__ V) {
    int c = blockIdx.x, bh = blockIdx.y;
    int d = threadIdx.x & 63, rg = threadIdx.x >> 6;
    int b = bh >> 4, h = bh & 15;
    float s = 0.f;
    #pragma unroll 8
    for (int r = rg * 32; r < rg * 32 + 32; ++r)
        s += V[(((size_t)b * Lc + c * BM + r) * Hc + h) * 64 + d];
    __shared__ float red[256];
    red[threadIdx.x] = s;
    __syncthreads();
    if (threadIdx.x < 64)
        g_csum[(bh * NCH + c) * 64 + d] = red[d] + red[64 + d] + red[128 + d] + red[192 + d];
}

// in-place exclusive suffix of chunk sums
__global__ void scan_offsets() {
    int i = blockIdx.x * 256 + threadIdx.x;          // 2048 columns
    int bh = i >> 6, d = i & 63;
    float v[NCH];
    #pragma unroll
    for (int c = 0; c < NCH; ++c) v[c] = g_csum[(bh * NCH + c) * 64 + d];
    float run = 0.f;
    #pragma unroll
    for (int c = NCH - 1; c >= 0; --c) {
        g_csum[(bh * NCH + c) * 64 + d] = run;
        run += v[c];
    }
}

// ---------------- main attention kernel ----------------
#define QSCALE 0.18033688011112042f   // 0.125 * log2(e)
#define SM_FULL0  (2 * TILE_B)        // full[2]: tx barriers
#define SM_EMPTY0 (2 * TILE_B + 16)   // empty[2]: 8 warp-arrival barriers
#define SM_TOTAL  (2 * TILE_B + 128)  // 65664 -> 2 CTAs/SM

extern __shared__ __align__(1024) char dynsm[];

// one s-tile: wait full -> QK MMAs -> exp/pack -> PV MMAs -> arrive empty -> (warp0) refill
template <bool MASKED>
__device__ __forceinline__ void tile_body(
    int t, int tmax, uint32_t sm, const unsigned char* kvbase,
    const uint32_t Qh[4][4], const uint32_t Ql[4][4],
    float Oa[8][4], float& den0, float& den1,
    int tid, int lane, int rowglob,
    int ks_row, uint32_t k_col, int vs_row, uint32_t v_col, uint32_t xo)
{
    const uint32_t par = (uint32_t)((t >> 1) & 1);
    const uint32_t sl  = (uint32_t)(t & 1) * 8;
    MBAR_WAIT(sm + SM_FULL0 + sl, par);

    const uint32_t stg = sm + (uint32_t)(t & 1) * TILE_B;
    const uint32_t khi_b = stg, klo_b = stg + 8192;
    const uint32_t vhi_b = stg + 16384, vlo_b = stg + 24576;

    // ---- S = Q Kt (3-way bf16 split) ----
    float S[8][4];
    #pragma unroll
    for (int i = 0; i < 8; ++i)
        #pragma unroll
        for (int j = 0; j < 4; ++j) S[i][j] = 0.f;

    #pragma unroll
    for (int kc = 0; kc < 4; ++kc) {
        #pragma unroll
        for (int nbp = 0; nbp < 4; ++nbp) {
            uint32_t off = (uint32_t)(nbp * 16 + ks_row) * 128
                         + (((uint32_t)kc * 32 + k_col) ^ xo);
            uint32_t kb[4], kl4[4];
            ldsm4(khi_b + off, kb);
            ldsm4(klo_b + off, kl4);
            mma16816(S[2*nbp],   Qh[kc], kb[0], kb[1]);
            mma16816(S[2*nbp+1], Qh[kc], kb[2], kb[3]);
            mma16816(S[2*nbp],   Ql[kc], kb[0], kb[1]);
            mma16816(S[2*nbp+1], Ql[kc], kb[2], kb[3]);
            mma16816(S[2*nbp],   Qh[kc], kl4[0], kl4[1]);
            mma16816(S[2*nbp+1], Qh[kc], kl4[2], kl4[3]);
        }
    }

    // ---- exp; masked (future) slots contribute exp(0)=1 (reference semantics) ----
    const int quad = lane & 3;
    const int lim0 = MASKED ? (rowglob - (t << 6)) : 0;
    const int lim1 = lim0 + 8;
    uint32_t Ph[4][4], Pl[4][4];
    #pragma unroll
    for (int nb = 0; nb < 8; ++nb) {
        float p0, p1, p2, p3;
        if (MASKED) {
            int s0 = nb * 8 + quad * 2;
            p0 = (s0     <= lim0) ? ex2f(S[nb][0]) : 1.f;
            p1 = (s0 + 1 <= lim0) ? ex2f(S[nb][1]) : 1.f;
            p2 = (s0     <= lim1) ? ex2f(S[nb][2]) : 1.f;
            p3 = (s0 + 1 <= lim1) ? ex2f(S[nb][3]) : 1.f;
        } else {
            p0 = ex2f(S[nb][0]);
            p1 = ex2f(S[nb][1]);
            p2 = ex2f(S[nb][2]);
            p3 = ex2f(S[nb][3]);
        }
        den0 += p0 + p1;
        den1 += p2 + p3;
        split2(p0, p1, Ph[nb >> 1][(nb & 1) * 2],     Pl[nb >> 1][(nb & 1) * 2]);
        split2(p2, p3, Ph[nb >> 1][(nb & 1) * 2 + 1], Pl[nb >> 1][(nb & 1) * 2 + 1]);
    }

    // ---- O += P V (3-way bf16 split) ----
    #pragma unroll
    for (int kcs = 0; kcs < 4; ++kcs) {
        #pragma unroll
        for (int nbp = 0; nbp < 4; ++nbp) {
            uint32_t off = (uint32_t)(kcs * 16 + vs_row) * 128
                         + (((uint32_t)nbp * 32 + v_col) ^ xo);
            uint32_t vb[4], vl4[4];
            ldsm4t(vhi_b + off, vb);
            ldsm4t(vlo_b + off, vl4);
            mma16816(Oa[2*nbp],   Ph[kcs], vb[0], vb[1]);
            mma16816(Oa[2*nbp+1], Ph[kcs], vb[2], vb[3]);
            mma16816(Oa[2*nbp],   Pl[kcs], vb[0], vb[1]);
            mma16816(Oa[2*nbp+1], Pl[kcs], vb[2], vb[3]);
            mma16816(Oa[2*nbp],   Ph[kcs], vl4[0], vl4[1]);
            mma16816(Oa[2*nbp+1], Ph[kcs], vl4[2], vl4[3]);
        }
    }

    // this warp is done reading stage (t&1)
    if (lane == 0) MBAR_ARRIVE(sm + SM_EMPTY0 + sl);

    // producer: refill stage once all 8 warps arrived
    if (tid == 0 && t + 2 <= tmax) {
        MBAR_WAIT(sm + SM_EMPTY0 + sl, par);
        MBAR_EXPECT_TX(sm + SM_FULL0 + sl, TILE_B);
        bulk_ld(stg, kvbase + (size_t)(t + 2) * TILE_B, TILE_B, sm + SM_FULL0 + sl);
    }
}

__global__ void __launch_bounds__(256, 2) attn_mma(const float* __restrict__ Q,
                                                   float* __restrict__ O) {
    const uint32_t sm = smem_u32(dynsm);
    const int tid = threadIdx.x;
    const int w = tid >> 5, lane = tid & 31;
    const int g = lane >> 2, quad = lane & 3;
    const int bh = blockIdx.y, b = bh >> 4, h = bh & 15;
    const int mtile = (NQT - 1) - (int)blockIdx.x;   // heavy q-tiles first
    const int tmax = 2 * mtile + 1;                  // s tiles 0..tmax

    if (tid == 0) {
        MBAR_INIT(sm + SM_FULL0, 1);      MBAR_INIT(sm + SM_FULL0 + 8, 1);
        MBAR_INIT(sm + SM_EMPTY0, 8);     MBAR_INIT(sm + SM_EMPTY0 + 8, 8);
    }

    // per-lane ldmatrix geometry (XOR-swizzled, 128B rows)
    const int ks_row = (lane & 7) + ((lane >> 4) << 3);
    const uint32_t k_col = ((uint32_t)((lane >> 3) & 1)) * 16;
    const int vs_row = (lane & 7) + (((lane >> 3) & 1) << 3);
    const uint32_t v_col = ((uint32_t)(lane >> 4)) << 4;
    const uint32_t xo = ((uint32_t)(lane & 7)) << 4;

    // ---- Q fragments (hi/lo split, scale folded in) ----
    uint32_t Qh[4][4], Ql[4][4];
    {
        const float* qb = Q + (((size_t)b * Lc + (size_t)mtile * BM + w * 16) * Hc + h) * 64;
        #pragma unroll
        for (int kc = 0; kc < 4; ++kc) {
            int e0 = kc * 16 + quad * 2;
            float2 v00 = *(const float2*)(qb + (size_t)g * 1024 + e0);
            float2 v10 = *(const float2*)(qb + (size_t)(g + 8) * 1024 + e0);
            float2 v01 = *(const float2*)(qb + (size_t)g * 1024 + e0 + 8);
            float2 v11 = *(const float2*)(qb + (size_t)(g + 8) * 1024 + e0 + 8);
            split2(v00.x * QSCALE, v00.y * QSCALE, Qh[kc][0], Ql[kc][0]);
            split2(v10.x * QSCALE, v10.y * QSCALE, Qh[kc][1], Ql[kc][1]);
            split2(v01.x * QSCALE, v01.y * QSCALE, Qh[kc][2], Ql[kc][2]);
            split2(v11.x * QSCALE, v11.y * QSCALE, Qh[kc][3], Ql[kc][3]);
        }
    }
    __syncthreads();   // mbarrier init visible to all warps

    // prologue: issue tiles 0 and 1 (tmax >= 1 always)
    const unsigned char* kvbase = g_KV + (size_t)bh * NST * TILE_B;
    if (tid == 0) {
        MBAR_EXPECT_TX(sm + SM_FULL0, TILE_B);
        bulk_ld(sm, kvbase, TILE_B, sm + SM_FULL0);
        MBAR_EXPECT_TX(sm + SM_FULL0 + 8, TILE_B);
        bulk_ld(sm + TILE_B, kvbase + TILE_B, TILE_B, sm + SM_FULL0 + 8);
    }

    float Oa[8][4];
    #pragma unroll
    for (int i = 0; i < 8; ++i)
        #pragma unroll
        for (int j = 0; j < 4; ++j) Oa[i][j] = 0.f;
    float den0 = 0.f, den1 = 0.f;

    const int rowA = w * 16 + g;
    const int rowglob = mtile * BM + rowA;

    int t = 0;
    #pragma unroll 1
    for (; t <= tmax - 2; ++t)
        tile_body<false>(t, tmax, sm, kvbase, Qh, Ql, Oa, den0, den1,
                         tid, lane, rowglob, ks_row, k_col, vs_row, v_col, xo);
    #pragma unroll 1
    for (; t <= tmax; ++t)
        tile_body<true>(t, tmax, sm, kvbase, Qh, Ql, Oa, den0, den1,
                        tid, lane, rowglob, ks_row, k_col, vs_row, v_col, xo);

    // ---- epilogue ----
    den0 += __shfl_xor_sync(0xffffffffu, den0, 1);
    den0 += __shfl_xor_sync(0xffffffffu, den0, 2);
    den1 += __shfl_xor_sync(0xffffffffu, den1, 1);
    den1 += __shfl_xor_sync(0xffffffffu, den1, 2);

    const float corr = (float)(Lc - (mtile + 1) * BM);   // masked slots beyond processed tiles
    const float inv0 = 1.f / (den0 + corr);
    const float inv1 = 1.f / (den1 + corr);

    const int r0g = rowglob;
    const int r1g = r0g + 8;
    const size_t ob0 = (((size_t)b * Lc + r0g) * Hc + h) * 64;
    const size_t ob1 = (((size_t)b * Lc + r1g) * Hc + h) * 64;
    const float* sfx = &g_csum[(bh * NCH + mtile) * 64];

    #pragma unroll
    for (int nb = 0; nb < 8; ++nb) {
        int d0 = nb * 8 + quad * 2;
        float2 s2 = *(const float2*)(sfx + d0);
        float2 o0 = make_float2((Oa[nb][0] + s2.x) * inv0, (Oa[nb][1] + s2.y) * inv0);
        float2 o1 = make_float2((Oa[nb][2] + s2.x) * inv1, (Oa[nb][3] + s2.y) * inv1);
        *(float2*)&O[ob0 + d0] = o0;
        *(float2*)&O[ob1 + d0] = o1;
    }
}

// ---------------- launch ----------------
extern "C" void kernel_launch(void* const* d_in, const int* in_sizes, int n_in,
                              void* d_out, int out_size) {
    const float* Q = (const float*)d_in[0];
    const float* K = (const float*)d_in[1];
    const float* V = (const float*)d_in[2];
    float* O = (float*)d_out;

    convert_kv<<<2048, 256>>>(K, V);
    scan_chunks<<<dim3(NCH, BHc), 256>>>(V);
    scan_offsets<<<8, 256>>>();

    cudaFuncSetAttribute(attn_mma, cudaFuncAttributeMaxDynamicSharedMemorySize, SM_TOTAL);
    attn_mma<<<dim3(NQT, BHc), 256, SM_TOTAL>>>(Q, O);
}

// round 7
// speedup vs baseline: 1.6411x; 1.4060x over previous
#include <cuda_runtime.h>
#include <cuda_bf16.h>
#include <cstdint>

#define Bc 2
#define Lc 2048
#define Hc 16
#define BHc 32
#define BM 128                 // q-rows per CTA
#define BN 64                  // s-rows per tile
#define NQT 16                 // q tiles
#define NST 32                 // s tiles
#define NCH 16
#define TILE_B 24576           // packed tile: Khi(8K)|Klo(8K)|Vf16(8K)
#define NSTG 3                 // pipeline stages

// ---------------- device scratch ----------------
__device__ float g_csum[BHc * NCH * 64];                        // per-128-chunk V sums -> excl. suffix
__device__ unsigned char g_KV[(size_t)BHc * NST * TILE_B];      // pre-swizzled packed KV (24MB)

// ---------------- helpers ----------------
__device__ __forceinline__ uint32_t smem_u32(const void* p) {
    uint32_t a;
    asm("{ .reg .u64 t; cvta.to.shared.u64 t, %1; cvt.u32.u64 %0, t; }" : "=r"(a) : "l"(p));
    return a;
}
__device__ __forceinline__ float ex2f(float x) {
    float y; asm("ex2.approx.f32 %0, %1;" : "=f"(y) : "f"(x)); return y;
}
// hi/lo bf16 split: 2 packed cvts + 2 bitops + 2 subs
__device__ __forceinline__ void split2(float a, float b, uint32_t& hi, uint32_t& lo) {
    uint32_t h;
    asm("cvt.rn.bf16x2.f32 %0, %1, %2;" : "=r"(h) : "f"(b), "f"(a));   // hi16=b, lo16=a
    float fa = __uint_as_float(h << 16);
    float fb = __uint_as_float(h & 0xFFFF0000u);
    float ra = a - fa, rb = b - fb;
    asm("cvt.rn.bf16x2.f32 %0, %1, %2;" : "=r"(lo) : "f"(rb), "f"(ra));
    hi = h;
}
__device__ __forceinline__ uint32_t packf16(float lo, float hi) {
    uint32_t r;
    asm("cvt.rn.f16x2.f32 %0, %1, %2;" : "=r"(r) : "f"(hi), "f"(lo));
    return r;
}
__device__ __forceinline__ void mma16816(float* c, const uint32_t* a, uint32_t b0, uint32_t b1) {
    asm volatile("mma.sync.aligned.m16n8k16.row.col.f32.bf16.bf16.f32 "
        "{%0,%1,%2,%3}, {%4,%5,%6,%7}, {%8,%9}, {%0,%1,%2,%3};"
        : "+f"(c[0]), "+f"(c[1]), "+f"(c[2]), "+f"(c[3])
        : "r"(a[0]), "r"(a[1]), "r"(a[2]), "r"(a[3]), "r"(b0), "r"(b1));
}
__device__ __forceinline__ void mma16816h(float* c, const uint32_t* a, uint32_t b0, uint32_t b1) {
    asm volatile("mma.sync.aligned.m16n8k16.row.col.f32.f16.f16.f32 "
        "{%0,%1,%2,%3}, {%4,%5,%6,%7}, {%8,%9}, {%0,%1,%2,%3};"
        : "+f"(c[0]), "+f"(c[1]), "+f"(c[2]), "+f"(c[3])
        : "r"(a[0]), "r"(a[1]), "r"(a[2]), "r"(a[3]), "r"(b0), "r"(b1));
}
__device__ __forceinline__ void ldsm4(uint32_t addr, uint32_t* r) {
    asm volatile("ldmatrix.sync.aligned.m8n8.x4.shared.b16 {%0,%1,%2,%3}, [%4];"
        : "=r"(r[0]), "=r"(r[1]), "=r"(r[2]), "=r"(r[3]) : "r"(addr));
}
__device__ __forceinline__ void ldsm4t(uint32_t addr, uint32_t* r) {
    asm volatile("ldmatrix.sync.aligned.m8n8.x4.trans.shared.b16 {%0,%1,%2,%3}, [%4];"
        : "=r"(r[0]), "=r"(r[1]), "=r"(r[2]), "=r"(r[3]) : "r"(addr));
}
__device__ __forceinline__ void bulk_ld(uint32_t dst, const void* src, uint32_t bytes, uint32_t mbar) {
    asm volatile("cp.async.bulk.shared::cluster.global.mbarrier::complete_tx::bytes [%0], [%1], %2, [%3];"
        :: "r"(dst), "l"(src), "r"(bytes), "r"(mbar) : "memory");
}
#define MBAR_INIT(addr, cnt) \
    asm volatile("mbarrier.init.shared.b64 [%0], %1;" :: "r"((uint32_t)(addr)), "r"((uint32_t)(cnt)) : "memory")
#define MBAR_EXPECT_TX(addr, tx) \
    asm volatile("mbarrier.arrive.expect_tx.shared.b64 _, [%0], %1;" :: "r"((uint32_t)(addr)), "r"((uint32_t)(tx)) : "memory")
#define MBAR_ARRIVE(addr) \
    asm volatile("mbarrier.arrive.shared.b64 _, [%0];" :: "r"((uint32_t)(addr)) : "memory")
#define MBAR_WAIT(addr, par) do { \
    uint32_t _m = (uint32_t)(addr); uint32_t _p = (uint32_t)(par); uint32_t _d; \
    asm volatile("{ .reg .pred p; mbarrier.try_wait.parity.acquire.cta.shared::cta.b64 p, [%1], %2; selp.b32 %0,1,0,p; }" \
        : "=r"(_d) : "r"(_m), "r"(_p) : "memory"); \
    if (!_d) { \
        asm volatile("{ .reg .pred P1; WL_%=: mbarrier.try_wait.parity.acquire.cta.shared::cta.b64 P1, [%0], %1, 0x989680; @P1 bra.uni WD_%=; bra.uni WL_%=; WD_%=: }" \
            :: "r"(_m), "r"(_p) : "memory"); \
    } } while (0)

// ---------------- preprocessing ----------------

// K -> bf16 hi/lo, V -> single fp16; packed + XOR-swizzled, tile-contiguous
__global__ void convert_kv(const float* __restrict__ K, const float* __restrict__ V) {
    uint32_t n = blockIdx.x * 256 + threadIdx.x;     // 524288 threads
    int ch = n & 7;
    int s  = (n >> 3) & 2047;
    int bh = n >> 14;
    int b = bh >> 4, h = bh & 15;
    int t = s >> 6, sr = s & 63;

    size_t src = (((size_t)b * Lc + s) * Hc + h) * 64 + ch * 8;
    size_t tb = ((size_t)(bh * NST + t)) * TILE_B;
    uint32_t roff = (uint32_t)sr * 128 + (((uint32_t)ch * 16) ^ (((uint32_t)sr & 7) << 4));

    float4 k0 = *(const float4*)(K + src), k1 = *(const float4*)(K + src + 4);
    float4 v0 = *(const float4*)(V + src), v1 = *(const float4*)(V + src + 4);

    uint4 khi, klo, vh;
    split2(k0.x, k0.y, khi.x, klo.x); split2(k0.z, k0.w, khi.y, klo.y);
    split2(k1.x, k1.y, khi.z, klo.z); split2(k1.z, k1.w, khi.w, klo.w);
    vh.x = packf16(v0.x, v0.y); vh.y = packf16(v0.z, v0.w);
    vh.z = packf16(v1.x, v1.y); vh.w = packf16(v1.z, v1.w);

    *(uint4*)(g_KV + tb +     0 + roff) = khi;
    *(uint4*)(g_KV + tb +  8192 + roff) = klo;
    *(uint4*)(g_KV + tb + 16384 + roff) = vh;
}

// per-128-chunk V column sums
__global__ void scan_chunks(const float* __restrict__ V) {
    int c = blockIdx.x, bh = blockIdx.y;
    int d = threadIdx.x & 63, rg = threadIdx.x >> 6;
    int b = bh >> 4, h = bh & 15;
    float s = 0.f;
    #pragma unroll 8
    for (int r = rg * 32; r < rg * 32 + 32; ++r)
        s += V[(((size_t)b * Lc + c * BM + r) * Hc + h) * 64 + d];
    __shared__ float red[256];
    red[threadIdx.x] = s;
    __syncthreads();
    if (threadIdx.x < 64)
        g_csum[(bh * NCH + c) * 64 + d] = red[d] + red[64 + d] + red[128 + d] + red[192 + d];
}

// in-place exclusive suffix of chunk sums
__global__ void scan_offsets() {
    int i = blockIdx.x * 256 + threadIdx.x;          // 2048 columns
    int bh = i >> 6, d = i & 63;
    float v[NCH];
    #pragma unroll
    for (int c = 0; c < NCH; ++c) v[c] = g_csum[(bh * NCH + c) * 64 + d];
    float run = 0.f;
    #pragma unroll
    for (int c = NCH - 1; c >= 0; --c) {
        g_csum[(bh * NCH + c) * 64 + d] = run;
        run += v[c];
    }
}

// ---------------- main attention kernel ----------------
#define QSCALE 0.18033688011112042f   // 0.125 * log2(e)
#define SM_FULL0  (NSTG * TILE_B)         // full[3]: tx barriers (+0,+8,+16)
#define SM_EMPTY0 (NSTG * TILE_B + 32)    // empty[3]: 8 warp-arrival barriers
#define SM_TOTAL  (NSTG * TILE_B + 128)   // 73856 -> 2 CTAs/SM

extern __shared__ __align__(1024) char dynsm[];

// one s-tile: wait full -> QK MMAs -> exp/pack -> PV MMAs -> arrive empty -> (warp0) refill
template <bool MASKED>
__device__ __forceinline__ void tile_body(
    int t, int st, int rpar, int tmax, uint32_t sm, const unsigned char* kvbase,
    const uint32_t Qh[4][4], const uint32_t Ql[4][4],
    float Oa[8][4], float& den0, float& den1,
    int tid, int lane, int rowglob,
    int ks_row, uint32_t k_col, int vs_row, uint32_t v_col, uint32_t xo)
{
    MBAR_WAIT(sm + SM_FULL0 + st * 8, rpar);

    const uint32_t stg = sm + (uint32_t)st * TILE_B;
    const uint32_t khi_b = stg, klo_b = stg + 8192, v_b = stg + 16384;

    // ---- S = Q Kt (3-way bf16 split) ----
    float S[8][4];
    #pragma unroll
    for (int i = 0; i < 8; ++i)
        #pragma unroll
        for (int j = 0; j < 4; ++j) S[i][j] = 0.f;

    #pragma unroll
    for (int kc = 0; kc < 4; ++kc) {
        #pragma unroll
        for (int nbp = 0; nbp < 4; ++nbp) {
            uint32_t off = (uint32_t)(nbp * 16 + ks_row) * 128
                         + (((uint32_t)kc * 32 + k_col) ^ xo);
            uint32_t kb[4], kl4[4];
            ldsm4(khi_b + off, kb);
            ldsm4(klo_b + off, kl4);
            mma16816(S[2*nbp],   Qh[kc], kb[0], kb[1]);
            mma16816(S[2*nbp+1], Qh[kc], kb[2], kb[3]);
            mma16816(S[2*nbp],   Ql[kc], kb[0], kb[1]);
            mma16816(S[2*nbp+1], Ql[kc], kb[2], kb[3]);
            mma16816(S[2*nbp],   Qh[kc], kl4[0], kl4[1]);
            mma16816(S[2*nbp+1], Qh[kc], kl4[2], kl4[3]);
        }
    }

    // ---- exp; masked (future) slots contribute exp(0)=1 (reference semantics) ----
    const int quad = lane & 3;
    const int lim0 = MASKED ? (rowglob - (t << 6)) : 0;
    const int lim1 = lim0 + 8;
    uint32_t Ph[4][4];
    #pragma unroll
    for (int nb = 0; nb < 8; ++nb) {
        float p0, p1, p2, p3;
        if (MASKED) {
            int s0 = nb * 8 + quad * 2;
            p0 = (s0     <= lim0) ? ex2f(S[nb][0]) : 1.f;
            p1 = (s0 + 1 <= lim0) ? ex2f(S[nb][1]) : 1.f;
            p2 = (s0     <= lim1) ? ex2f(S[nb][2]) : 1.f;
            p3 = (s0 + 1 <= lim1) ? ex2f(S[nb][3]) : 1.f;
        } else {
            p0 = ex2f(S[nb][0]);
            p1 = ex2f(S[nb][1]);
            p2 = ex2f(S[nb][2]);
            p3 = ex2f(S[nb][3]);
        }
        den0 += p0 + p1;
        den1 += p2 + p3;
        Ph[nb >> 1][(nb & 1) * 2]     = packf16(p0, p1);
        Ph[nb >> 1][(nb & 1) * 2 + 1] = packf16(p2, p3);
    }

    // ---- O += P V (single fp16) ----
    #pragma unroll
    for (int kcs = 0; kcs < 4; ++kcs) {
        #pragma unroll
        for (int nbp = 0; nbp < 4; ++nbp) {
            uint32_t off = (uint32_t)(kcs * 16 + vs_row) * 128
                         + (((uint32_t)nbp * 32 + v_col) ^ xo);
            uint32_t vb[4];
            ldsm4t(v_b + off, vb);
            mma16816h(Oa[2*nbp],   Ph[kcs], vb[0], vb[1]);
            mma16816h(Oa[2*nbp+1], Ph[kcs], vb[2], vb[3]);
        }
    }

    // this warp is done reading stage st
    if (lane == 0) MBAR_ARRIVE(sm + SM_EMPTY0 + st * 8);

    // producer: refill stage once all 8 warps arrived
    if (tid == 0 && t + NSTG <= tmax) {
        MBAR_WAIT(sm + SM_EMPTY0 + st * 8, rpar);
        MBAR_EXPECT_TX(sm + SM_FULL0 + st * 8, TILE_B);
        bulk_ld(stg, kvbase + (size_t)(t + NSTG) * TILE_B, TILE_B, sm + SM_FULL0 + st * 8);
    }
}

__global__ void __launch_bounds__(256, 2) attn_mma(const float* __restrict__ Q,
                                                   float* __restrict__ O) {
    const uint32_t sm = smem_u32(dynsm);
    const int tid = threadIdx.x;
    const int w = tid >> 5, lane = tid & 31;
    const int g = lane >> 2, quad = lane & 3;
    const int bh = blockIdx.y, b = bh >> 4, h = bh & 15;
    const int mtile = (NQT - 1) - (int)blockIdx.x;   // heavy q-tiles first
    const int tmax = 2 * mtile + 1;                  // s tiles 0..tmax

    if (tid == 0) {
        #pragma unroll
        for (int s = 0; s < NSTG; ++s) {
            MBAR_INIT(sm + SM_FULL0 + s * 8, 1);
            MBAR_INIT(sm + SM_EMPTY0 + s * 8, 8);
        }
    }

    // per-lane ldmatrix geometry (XOR-swizzled, 128B rows)
    const int ks_row = (lane & 7) + ((lane >> 4) << 3);
    const uint32_t k_col = ((uint32_t)((lane >> 3) & 1)) * 16;
    const int vs_row = (lane & 7) + (((lane >> 3) & 1) << 3);
    const uint32_t v_col = ((uint32_t)(lane >> 4)) << 4;
    const uint32_t xo = ((uint32_t)(lane & 7)) << 4;

    // ---- Q fragments (hi/lo split, scale folded in) ----
    uint32_t Qh[4][4], Ql[4][4];
    {
        const float* qb = Q + (((size_t)b * Lc + (size_t)mtile * BM + w * 16) * Hc + h) * 64;
        #pragma unroll
        for (int kc = 0; kc < 4; ++kc) {
            int e0 = kc * 16 + quad * 2;
            float2 v00 = *(const float2*)(qb + (size_t)g * 1024 + e0);
            float2 v10 = *(const float2*)(qb + (size_t)(g + 8) * 1024 + e0);
            float2 v01 = *(const float2*)(qb + (size_t)g * 1024 + e0 + 8);
            float2 v11 = *(const float2*)(qb + (size_t)(g + 8) * 1024 + e0 + 8);
            split2(v00.x * QSCALE, v00.y * QSCALE, Qh[kc][0], Ql[kc][0]);
            split2(v10.x * QSCALE, v10.y * QSCALE, Qh[kc][1], Ql[kc][1]);
            split2(v01.x * QSCALE, v01.y * QSCALE, Qh[kc][2], Ql[kc][2]);
            split2(v11.x * QSCALE, v11.y * QSCALE, Qh[kc][3], Ql[kc][3]);
        }
    }
    __syncthreads();   // mbarrier init visible to all warps

    // prologue: fill the ring
    const unsigned char* kvbase = g_KV + (size_t)bh * NST * TILE_B;
    if (tid == 0) {
        #pragma unroll
        for (int s = 0; s < NSTG; ++s) {
            if (s <= tmax) {
                MBAR_EXPECT_TX(sm + SM_FULL0 + s * 8, TILE_B);
                bulk_ld(sm + s * TILE_B, kvbase + (size_t)s * TILE_B, TILE_B,
                        sm + SM_FULL0 + s * 8);
            }
        }
    }

    float Oa[8][4];
    #pragma unroll
    for (int i = 0; i < 8; ++i)
        #pragma unroll
        for (int j = 0; j < 4; ++j) Oa[i][j] = 0.f;
    float den0 = 0.f, den1 = 0.f;

    const int rowA = w * 16 + g;
    const int rowglob = mtile * BM + rowA;

    int t = 0, st = 0, rp = 0;
    #pragma unroll 1
    for (; t <= tmax - 2; ++t) {
        tile_body<false>(t, st, rp, tmax, sm, kvbase, Qh, Ql, Oa, den0, den1,
                         tid, lane, rowglob, ks_row, k_col, vs_row, v_col, xo);
        if (++st == NSTG) { st = 0; rp ^= 1; }
    }
    #pragma unroll 1
    for (; t <= tmax; ++t) {
        tile_body<true>(t, st, rp, tmax, sm, kvbase, Qh, Ql, Oa, den0, den1,
                        tid, lane, rowglob, ks_row, k_col, vs_row, v_col, xo);
        if (++st == NSTG) { st = 0; rp ^= 1; }
    }

    // ---- epilogue ----
    den0 += __shfl_xor_sync(0xffffffffu, den0, 1);
    den0 += __shfl_xor_sync(0xffffffffu, den0, 2);
    den1 += __shfl_xor_sync(0xffffffffu, den1, 1);
    den1 += __shfl_xor_sync(0xffffffffu, den1, 2);

    const float corr = (float)(Lc - (mtile + 1) * BM);   // masked slots beyond processed tiles
    const float inv0 = 1.f / (den0 + corr);
    const float inv1 = 1.f / (den1 + corr);

    const int r0g = rowglob;
    const int r1g = r0g + 8;
    const size_t ob0 = (((size_t)b * Lc + r0g) * Hc + h) * 64;
    const size_t ob1 = (((size_t)b * Lc + r1g) * Hc + h) * 64;
    const float* sfx = &g_csum[(bh * NCH + mtile) * 64];

    #pragma unroll
    for (int nb = 0; nb < 8; ++nb) {
        int d0 = nb * 8 + quad * 2;
        float2 s2 = *(const float2*)(sfx + d0);
        float2 o0 = make_float2((Oa[nb][0] + s2.x) * inv0, (Oa[nb][1] + s2.y) * inv0);
        float2 o1 = make_float2((Oa[nb][2] + s2.x) * inv1, (Oa[nb][3] + s2.y) * inv1);
        *(float2*)&O[ob0 + d0] = o0;
        *(float2*)&O[ob1 + d0] = o1;
    }
}

// ---------------- launch ----------------
extern "C" void kernel_launch(void* const* d_in, const int* in_sizes, int n_in,
                              void* d_out, int out_size) {
    const float* Q = (const float*)d_in[0];
    const float* K = (const float*)d_in[1];
    const float* V = (const float*)d_in[2];
    float* O = (float*)d_out;

    convert_kv<<<2048, 256>>>(K, V);
    scan_chunks<<<dim3(NCH, BHc), 256>>>(V);
    scan_offsets<<<8, 256>>>();

    cudaFuncSetAttribute(attn_mma, cudaFuncAttributeMaxDynamicSharedMemorySize, SM_TOTAL);
    attn_mma<<<dim3(NQT, BHc), 256, SM_TOTAL>>>(Q, O);
}

// round 8
// speedup vs baseline: 2.7922x; 1.7014x over previous
#include <cuda_runtime.h>
#include <cuda_bf16.h>
#include <cstdint>

#define Bc 2
#define Lc 2048
#define Hc 16
#define BHc 32
#define BM 128                 // q-rows per CTA
#define BN 64                  // s-rows per tile
#define NQT 16                 // q tiles
#define NST 32                 // s tiles
#define NCH 16
#define TILE_B 16384           // packed tile: Kf16(8K)|Vf16(8K)
#define NSTG 4                 // pipeline stages

// ---------------- device scratch ----------------
__device__ float g_csum[BHc * NCH * 64];                        // per-128-chunk V sums -> excl. suffix
__device__ unsigned char g_KV[(size_t)BHc * NST * TILE_B];      // pre-swizzled packed KV (16MB)

// ---------------- helpers ----------------
__device__ __forceinline__ uint32_t smem_u32(const void* p) {
    uint32_t a;
    asm("{ .reg .u64 t; cvta.to.shared.u64 t, %1; cvt.u32.u64 %0, t; }" : "=r"(a) : "l"(p));
    return a;
}
__device__ __forceinline__ float ex2f(float x) {
    float y; asm("ex2.approx.f32 %0, %1;" : "=f"(y) : "f"(x)); return y;
}
__device__ __forceinline__ uint32_t packf16(float lo, float hi) {
    uint32_t r;
    asm("cvt.rn.f16x2.f32 %0, %1, %2;" : "=r"(r) : "f"(hi), "f"(lo));
    return r;
}
__device__ __forceinline__ void mma16816h(float* c, const uint32_t* a, uint32_t b0, uint32_t b1) {
    asm volatile("mma.sync.aligned.m16n8k16.row.col.f32.f16.f16.f32 "
        "{%0,%1,%2,%3}, {%4,%5,%6,%7}, {%8,%9}, {%0,%1,%2,%3};"
        : "+f"(c[0]), "+f"(c[1]), "+f"(c[2]), "+f"(c[3])
        : "r"(a[0]), "r"(a[1]), "r"(a[2]), "r"(a[3]), "r"(b0), "r"(b1));
}
__device__ __forceinline__ void ldsm4(uint32_t addr, uint32_t* r) {
    asm volatile("ldmatrix.sync.aligned.m8n8.x4.shared.b16 {%0,%1,%2,%3}, [%4];"
        : "=r"(r[0]), "=r"(r[1]), "=r"(r[2]), "=r"(r[3]) : "r"(addr));
}
__device__ __forceinline__ void ldsm4t(uint32_t addr, uint32_t* r) {
    asm volatile("ldmatrix.sync.aligned.m8n8.x4.trans.shared.b16 {%0,%1,%2,%3}, [%4];"
        : "=r"(r[0]), "=r"(r[1]), "=r"(r[2]), "=r"(r[3]) : "r"(addr));
}
__device__ __forceinline__ void bulk_ld(uint32_t dst, const void* src, uint32_t bytes, uint32_t mbar) {
    asm volatile("cp.async.bulk.shared::cluster.global.mbarrier::complete_tx::bytes [%0], [%1], %2, [%3];"
        :: "r"(dst), "l"(src), "r"(bytes), "r"(mbar) : "memory");
}
#define MBAR_INIT(addr, cnt) \
    asm volatile("mbarrier.init.shared.b64 [%0], %1;" :: "r"((uint32_t)(addr)), "r"((uint32_t)(cnt)) : "memory")
#define MBAR_EXPECT_TX(addr, tx) \
    asm volatile("mbarrier.arrive.expect_tx.shared.b64 _, [%0], %1;" :: "r"((uint32_t)(addr)), "r"((uint32_t)(tx)) : "memory")
#define MBAR_ARRIVE(addr) \
    asm volatile("mbarrier.arrive.shared.b64 _, [%0];" :: "r"((uint32_t)(addr)) : "memory")
#define MBAR_WAIT(addr, par) do { \
    uint32_t _m = (uint32_t)(addr); uint32_t _p = (uint32_t)(par); uint32_t _d; \
    asm volatile("{ .reg .pred p; mbarrier.try_wait.parity.acquire.cta.shared::cta.b64 p, [%1], %2; selp.b32 %0,1,0,p; }" \
        : "=r"(_d) : "r"(_m), "r"(_p) : "memory"); \
    if (!_d) { \
        asm volatile("{ .reg .pred P1; WL_%=: mbarrier.try_wait.parity.acquire.cta.shared::cta.b64 P1, [%0], %1, 0x989680; @P1 bra.uni WD_%=; bra.uni WL_%=; WD_%=: }" \
            :: "r"(_m), "r"(_p) : "memory"); \
    } } while (0)

// ---------------- preprocessing ----------------

// K,V -> single fp16; packed + XOR-swizzled, tile-contiguous [bh][t64][K|V][sr][128B]
__global__ void convert_kv(const float* __restrict__ K, const float* __restrict__ V) {
    uint32_t n = blockIdx.x * 256 + threadIdx.x;     // 524288 threads
    int ch = n & 7;
    int s  = (n >> 3) & 2047;
    int bh = n >> 14;
    int b = bh >> 4, h = bh & 15;
    int t = s >> 6, sr = s & 63;

    size_t src = (((size_t)b * Lc + s) * Hc + h) * 64 + ch * 8;
    size_t tb = ((size_t)(bh * NST + t)) * TILE_B;
    uint32_t roff = (uint32_t)sr * 128 + (((uint32_t)ch * 16) ^ (((uint32_t)sr & 7) << 4));

    float4 k0 = *(const float4*)(K + src), k1 = *(const float4*)(K + src + 4);
    float4 v0 = *(const float4*)(V + src), v1 = *(const float4*)(V + src + 4);

    uint4 kh, vh;
    kh.x = packf16(k0.x, k0.y); kh.y = packf16(k0.z, k0.w);
    kh.z = packf16(k1.x, k1.y); kh.w = packf16(k1.z, k1.w);
    vh.x = packf16(v0.x, v0.y); vh.y = packf16(v0.z, v0.w);
    vh.z = packf16(v1.x, v1.y); vh.w = packf16(v1.z, v1.w);

    *(uint4*)(g_KV + tb +    0 + roff) = kh;
    *(uint4*)(g_KV + tb + 8192 + roff) = vh;
}

// per-128-chunk V column sums
__global__ void scan_chunks(const float* __restrict__ V) {
    int c = blockIdx.x, bh = blockIdx.y;
    int d = threadIdx.x & 63, rg = threadIdx.x >> 6;
    int b = bh >> 4, h = bh & 15;
    float s = 0.f;
    #pragma unroll 8
    for (int r = rg * 32; r < rg * 32 + 32; ++r)
        s += V[(((size_t)b * Lc + c * BM + r) * Hc + h) * 64 + d];
    __shared__ float red[256];
    red[threadIdx.x] = s;
    __syncthreads();
    if (threadIdx.x < 64)
        g_csum[(bh * NCH + c) * 64 + d] = red[d] + red[64 + d] + red[128 + d] + red[192 + d];
}

// in-place exclusive suffix of chunk sums
__global__ void scan_offsets() {
    int i = blockIdx.x * 256 + threadIdx.x;          // 2048 columns
    int bh = i >> 6, d = i & 63;
    float v[NCH];
    #pragma unroll
    for (int c = 0; c < NCH; ++c) v[c] = g_csum[(bh * NCH + c) * 64 + d];
    float run = 0.f;
    #pragma unroll
    for (int c = NCH - 1; c >= 0; --c) {
        g_csum[(bh * NCH + c) * 64 + d] = run;
        run += v[c];
    }
}

// ---------------- main attention kernel ----------------
#define QSCALE 0.18033688011112042f   // 0.125 * log2(e)
#define SM_FULL0  (NSTG * TILE_B)         // full[4]: tx barriers (+0,+8,+16,+24)
#define SM_EMPTY0 (NSTG * TILE_B + 32)    // empty[4]: 8 warp-arrival barriers
#define SM_TOTAL  (NSTG * TILE_B + 128)   // 65664 -> 2 CTAs/SM

extern __shared__ __align__(1024) char dynsm[];

// one s-tile: wait full -> QK MMAs -> exp/pack -> PV MMAs -> arrive empty -> (warp0) refill
template <bool MASKED>
__device__ __forceinline__ void tile_body(
    int t, int st, int rpar, int tmax, uint32_t sm, const unsigned char* kvbase,
    const uint32_t Qh[4][4],
    float Oa[8][4], float& den0, float& den1,
    int tid, int lane, int rowglob,
    int ks_row, uint32_t k_col, int vs_row, uint32_t v_col, uint32_t xo)
{
    MBAR_WAIT(sm + SM_FULL0 + st * 8, rpar);

    const uint32_t stg = sm + (uint32_t)st * TILE_B;
    const uint32_t k_b = stg, v_b = stg + 8192;

    // ---- S = Q Kt (single fp16) ----
    float S[8][4];
    #pragma unroll
    for (int i = 0; i < 8; ++i)
        #pragma unroll
        for (int j = 0; j < 4; ++j) S[i][j] = 0.f;

    #pragma unroll
    for (int kc = 0; kc < 4; ++kc) {
        #pragma unroll
        for (int nbp = 0; nbp < 4; ++nbp) {
            uint32_t off = (uint32_t)(nbp * 16 + ks_row) * 128
                         + (((uint32_t)kc * 32 + k_col) ^ xo);
            uint32_t kb[4];
            ldsm4(k_b + off, kb);
            mma16816h(S[2*nbp],   Qh[kc], kb[0], kb[1]);
            mma16816h(S[2*nbp+1], Qh[kc], kb[2], kb[3]);
        }
    }

    // ---- exp; masked (future) slots contribute exp(0)=1 (reference semantics) ----
    const int quad = lane & 3;
    const int lim0 = MASKED ? (rowglob - (t << 6)) : 0;
    const int lim1 = lim0 + 8;
    uint32_t Ph[4][4];
    #pragma unroll
    for (int nb = 0; nb < 8; ++nb) {
        float p0, p1, p2, p3;
        if (MASKED) {
            int s0 = nb * 8 + quad * 2;
            p0 = (s0     <= lim0) ? ex2f(S[nb][0]) : 1.f;
            p1 = (s0 + 1 <= lim0) ? ex2f(S[nb][1]) : 1.f;
            p2 = (s0     <= lim1) ? ex2f(S[nb][2]) : 1.f;
            p3 = (s0 + 1 <= lim1) ? ex2f(S[nb][3]) : 1.f;
        } else {
            p0 = ex2f(S[nb][0]);
            p1 = ex2f(S[nb][1]);
            p2 = ex2f(S[nb][2]);
            p3 = ex2f(S[nb][3]);
        }
        den0 += p0 + p1;
        den1 += p2 + p3;
        Ph[nb >> 1][(nb & 1) * 2]     = packf16(p0, p1);
        Ph[nb >> 1][(nb & 1) * 2 + 1] = packf16(p2, p3);
    }

    // ---- O += P V (single fp16) ----
    #pragma unroll
    for (int kcs = 0; kcs < 4; ++kcs) {
        #pragma unroll
        for (int nbp = 0; nbp < 4; ++nbp) {
            uint32_t off = (uint32_t)(kcs * 16 + vs_row) * 128
                         + (((uint32_t)nbp * 32 + v_col) ^ xo);
            uint32_t vb[4];
            ldsm4t(v_b + off, vb);
            mma16816h(Oa[2*nbp],   Ph[kcs], vb[0], vb[1]);
            mma16816h(Oa[2*nbp+1], Ph[kcs], vb[2], vb[3]);
        }
    }

    // this warp is done reading stage st
    if (lane == 0) MBAR_ARRIVE(sm + SM_EMPTY0 + st * 8);

    // producer: refill stage once all 8 warps arrived
    if (tid == 0 && t + NSTG <= tmax) {
        MBAR_WAIT(sm + SM_EMPTY0 + st * 8, rpar);
        MBAR_EXPECT_TX(sm + SM_FULL0 + st * 8, TILE_B);
        bulk_ld(stg, kvbase + (size_t)(t + NSTG) * TILE_B, TILE_B, sm + SM_FULL0 + st * 8);
    }
}

__global__ void __launch_bounds__(256, 2) attn_mma(const float* __restrict__ Q,
                                                   float* __restrict__ O) {
    const uint32_t sm = smem_u32(dynsm);
    const int tid = threadIdx.x;
    const int w = tid >> 5, lane = tid & 31;
    const int g = lane >> 2, quad = lane & 3;
    const int bh = blockIdx.y, b = bh >> 4, h = bh & 15;
    const int mtile = (NQT - 1) - (int)blockIdx.x;   // heavy q-tiles first
    const int tmax = 2 * mtile + 1;                  // s tiles 0..tmax

    if (tid == 0) {
        #pragma unroll
        for (int s = 0; s < NSTG; ++s) {
            MBAR_INIT(sm + SM_FULL0 + s * 8, 1);
            MBAR_INIT(sm + SM_EMPTY0 + s * 8, 8);
        }
    }

    // per-lane ldmatrix geometry (XOR-swizzled, 128B rows)
    const int ks_row = (lane & 7) + ((lane >> 4) << 3);
    const uint32_t k_col = ((uint32_t)((lane >> 3) & 1)) * 16;
    const int vs_row = (lane & 7) + (((lane >> 3) & 1) << 3);
    const uint32_t v_col = ((uint32_t)(lane >> 4)) << 4;
    const uint32_t xo = ((uint32_t)(lane & 7)) << 4;

    // ---- Q fragments (single fp16, scale folded in) ----
    uint32_t Qh[4][4];
    {
        const float* qb = Q + (((size_t)b * Lc + (size_t)mtile * BM + w * 16) * Hc + h) * 64;
        #pragma unroll
        for (int kc = 0; kc < 4; ++kc) {
            int e0 = kc * 16 + quad * 2;
            float2 v00 = *(const float2*)(qb + (size_t)g * 1024 + e0);
            float2 v10 = *(const float2*)(qb + (size_t)(g + 8) * 1024 + e0);
            float2 v01 = *(const float2*)(qb + (size_t)g * 1024 + e0 + 8);
            float2 v11 = *(const float2*)(qb + (size_t)(g + 8) * 1024 + e0 + 8);
            Qh[kc][0] = packf16(v00.x * QSCALE, v00.y * QSCALE);
            Qh[kc][1] = packf16(v10.x * QSCALE, v10.y * QSCALE);
            Qh[kc][2] = packf16(v01.x * QSCALE, v01.y * QSCALE);
            Qh[kc][3] = packf16(v11.x * QSCALE, v11.y * QSCALE);
        }
    }
    __syncthreads();   // mbarrier init visible to all warps

    // prologue: fill the ring
    const unsigned char* kvbase = g_KV + (size_t)bh * NST * TILE_B;
    if (tid == 0) {
        #pragma unroll
        for (int s = 0; s < NSTG; ++s) {
            if (s <= tmax) {
                MBAR_EXPECT_TX(sm + SM_FULL0 + s * 8, TILE_B);
                bulk_ld(sm + s * TILE_B, kvbase + (size_t)s * TILE_B, TILE_B,
                        sm + SM_FULL0 + s * 8);
            }
        }
    }

    float Oa[8][4];
    #pragma unroll
    for (int i = 0; i < 8; ++i)
        #pragma unroll
        for (int j = 0; j < 4; ++j) Oa[i][j] = 0.f;
    float den0 = 0.f, den1 = 0.f;

    const int rowA = w * 16 + g;
    const int rowglob = mtile * BM + rowA;

    int t = 0, st = 0, rp = 0;
    #pragma unroll 1
    for (; t <= tmax - 2; ++t) {
        tile_body<false>(t, st, rp, tmax, sm, kvbase, Qh, Oa, den0, den1,
                         tid, lane, rowglob, ks_row, k_col, vs_row, v_col, xo);
        if (++st == NSTG) { st = 0; rp ^= 1; }
    }
    #pragma unroll 1
    for (; t <= tmax; ++t) {
        tile_body<true>(t, st, rp, tmax, sm, kvbase, Qh, Oa, den0, den1,
                        tid, lane, rowglob, ks_row, k_col, vs_row, v_col, xo);
        if (++st == NSTG) { st = 0; rp ^= 1; }
    }

    // ---- epilogue ----
    den0 += __shfl_xor_sync(0xffffffffu, den0, 1);
    den0 += __shfl_xor_sync(0xffffffffu, den0, 2);
    den1 += __shfl_xor_sync(0xffffffffu, den1, 1);
    den1 += __shfl_xor_sync(0xffffffffu, den1, 2);

    const float corr = (float)(Lc - (mtile + 1) * BM);   // masked slots beyond processed tiles
    const float inv0 = 1.f / (den0 + corr);
    const float inv1 = 1.f / (den1 + corr);

    const int r0g = rowglob;
    const int r1g = r0g + 8;
    const size_t ob0 = (((size_t)b * Lc + r0g) * Hc + h) * 64;
    const size_t ob1 = (((size_t)b * Lc + r1g) * Hc + h) * 64;
    const float* sfx = &g_csum[(bh * NCH + mtile) * 64];

    #pragma unroll
    for (int nb = 0; nb < 8; ++nb) {
        int d0 = nb * 8 + quad * 2;
        float2 s2 = *(const float2*)(sfx + d0);
        float2 o0 = make_float2((Oa[nb][0] + s2.x) * inv0, (Oa[nb][1] + s2.y) * inv0);
        float2 o1 = make_float2((Oa[nb][2] + s2.x) * inv1, (Oa[nb][3] + s2.y) * inv1);
        *(float2*)&O[ob0 + d0] = o0;
        *(float2*)&O[ob1 + d0] = o1;
    }
}

// ---------------- launch ----------------
extern "C" void kernel_launch(void* const* d_in, const int* in_sizes, int n_in,
                              void* d_out, int out_size) {
    const float* Q = (const float*)d_in[0];
    const float* K = (const float*)d_in[1];
    const float* V = (const float*)d_in[2];
    float* O = (float*)d_out;

    convert_kv<<<2048, 256>>>(K, V);
    scan_chunks<<<dim3(NCH, BHc), 256>>>(V);
    scan_offsets<<<8, 256>>>();

    cudaFuncSetAttribute(attn_mma, cudaFuncAttributeMaxDynamicSharedMemorySize, SM_TOTAL);
    attn_mma<<<dim3(NQT, BHc), 256, SM_TOTAL>>>(Q, O);
}

// round 9
// speedup vs baseline: 2.8927x; 1.0360x over previous
#include <cuda_runtime.h>
#include <cuda_bf16.h>
#include <cstdint>

#define Bc 2
#define Lc 2048
#define Hc 16
#define BHc 32
#define BM 128                 // q-rows per CTA
#define BN 64                  // s-rows per tile
#define NQT 16                 // q tiles
#define NST 32                 // s tiles
#define NCH 32                 // 64-row V-sum chunks
#define TILE_B 16384           // packed tile: Kf16(8K)|Vf16(8K)
#define NSTG 4                 // pipeline stages

// ---------------- device scratch ----------------
__device__ float g_csum[BHc * NCH * 64];                        // per-64-chunk V sums -> excl. suffix
__device__ unsigned char g_KV[(size_t)BHc * NST * TILE_B];      // pre-swizzled packed KV (16MB)

// ---------------- helpers ----------------
__device__ __forceinline__ uint32_t smem_u32(const void* p) {
    uint32_t a;
    asm("{ .reg .u64 t; cvta.to.shared.u64 t, %1; cvt.u32.u64 %0, t; }" : "=r"(a) : "l"(p));
    return a;
}
__device__ __forceinline__ float ex2f(float x) {
    float y; asm("ex2.approx.f32 %0, %1;" : "=f"(y) : "f"(x)); return y;
}
__device__ __forceinline__ uint32_t packf16(float lo, float hi) {
    uint32_t r;
    asm("cvt.rn.f16x2.f32 %0, %1, %2;" : "=r"(r) : "f"(hi), "f"(lo));
    return r;
}
__device__ __forceinline__ void mma16816h(float* c, const uint32_t* a, uint32_t b0, uint32_t b1) {
    asm volatile("mma.sync.aligned.m16n8k16.row.col.f32.f16.f16.f32 "
        "{%0,%1,%2,%3}, {%4,%5,%6,%7}, {%8,%9}, {%0,%1,%2,%3};"
        : "+f"(c[0]), "+f"(c[1]), "+f"(c[2]), "+f"(c[3])
        : "r"(a[0]), "r"(a[1]), "r"(a[2]), "r"(a[3]), "r"(b0), "r"(b1));
}
__device__ __forceinline__ void ldsm4(uint32_t addr, uint32_t* r) {
    asm volatile("ldmatrix.sync.aligned.m8n8.x4.shared.b16 {%0,%1,%2,%3}, [%4];"
        : "=r"(r[0]), "=r"(r[1]), "=r"(r[2]), "=r"(r[3]) : "r"(addr));
}
__device__ __forceinline__ void ldsm4t(uint32_t addr, uint32_t* r) {
    asm volatile("ldmatrix.sync.aligned.m8n8.x4.trans.shared.b16 {%0,%1,%2,%3}, [%4];"
        : "=r"(r[0]), "=r"(r[1]), "=r"(r[2]), "=r"(r[3]) : "r"(addr));
}
__device__ __forceinline__ void bulk_ld(uint32_t dst, const void* src, uint32_t bytes, uint32_t mbar) {
    asm volatile("cp.async.bulk.shared::cluster.global.mbarrier::complete_tx::bytes [%0], [%1], %2, [%3];"
        :: "r"(dst), "l"(src), "r"(bytes), "r"(mbar) : "memory");
}
#define MBAR_INIT(addr, cnt) \
    asm volatile("mbarrier.init.shared.b64 [%0], %1;" :: "r"((uint32_t)(addr)), "r"((uint32_t)(cnt)) : "memory")
#define MBAR_EXPECT_TX(addr, tx) \
    asm volatile("mbarrier.arrive.expect_tx.shared.b64 _, [%0], %1;" :: "r"((uint32_t)(addr)), "r"((uint32_t)(tx)) : "memory")
#define MBAR_ARRIVE(addr) \
    asm volatile("mbarrier.arrive.shared.b64 _, [%0];" :: "r"((uint32_t)(addr)) : "memory")
#define MBAR_WAIT(addr, par) do { \
    uint32_t _m = (uint32_t)(addr); uint32_t _p = (uint32_t)(par); uint32_t _d; \
    asm volatile("{ .reg .pred p; mbarrier.try_wait.parity.acquire.cta.shared::cta.b64 p, [%1], %2; selp.b32 %0,1,0,p; }" \
        : "=r"(_d) : "r"(_m), "r"(_p) : "memory"); \
    if (!_d) { \
        asm volatile("{ .reg .pred P1; WL_%=: mbarrier.try_wait.parity.acquire.cta.shared::cta.b64 P1, [%0], %1, 0x989680; @P1 bra.uni WD_%=; bra.uni WL_%=; WD_%=: }" \
            :: "r"(_m), "r"(_p) : "memory"); \
    } } while (0)

// ---------------- preprocessing ----------------

// K,V -> single fp16; packed + XOR-swizzled, tile-contiguous [bh][t64][K|V][sr][128B]
__global__ void convert_kv(const float* __restrict__ K, const float* __restrict__ V) {
    uint32_t n = blockIdx.x * 256 + threadIdx.x;     // 524288 threads
    int ch = n & 7;
    int s  = (n >> 3) & 2047;
    int bh = n >> 14;
    int b = bh >> 4, h = bh & 15;
    int t = s >> 6, sr = s & 63;

    size_t src = (((size_t)b * Lc + s) * Hc + h) * 64 + ch * 8;
    size_t tb = ((size_t)(bh * NST + t)) * TILE_B;
    uint32_t roff = (uint32_t)sr * 128 + (((uint32_t)ch * 16) ^ (((uint32_t)sr & 7) << 4));

    float4 k0 = *(const float4*)(K + src), k1 = *(const float4*)(K + src + 4);
    float4 v0 = *(const float4*)(V + src), v1 = *(const float4*)(V + src + 4);

    uint4 kh, vh;
    kh.x = packf16(k0.x, k0.y); kh.y = packf16(k0.z, k0.w);
    kh.z = packf16(k1.x, k1.y); kh.w = packf16(k1.z, k1.w);
    vh.x = packf16(v0.x, v0.y); vh.y = packf16(v0.z, v0.w);
    vh.z = packf16(v1.x, v1.y); vh.w = packf16(v1.z, v1.w);

    *(uint4*)(g_KV + tb +    0 + roff) = kh;
    *(uint4*)(g_KV + tb + 8192 + roff) = vh;
}

// per-64-chunk V column sums
__global__ void scan_chunks(const float* __restrict__ V) {
    int c = blockIdx.x, bh = blockIdx.y;
    int d = threadIdx.x & 63, rg = threadIdx.x >> 6;
    int b = bh >> 4, h = bh & 15;
    float s = 0.f;
    #pragma unroll 8
    for (int r = rg * 16; r < rg * 16 + 16; ++r)
        s += V[(((size_t)b * Lc + c * BN + r) * Hc + h) * 64 + d];
    __shared__ float red[256];
    red[threadIdx.x] = s;
    __syncthreads();
    if (threadIdx.x < 64)
        g_csum[(bh * NCH + c) * 64 + d] = red[d] + red[64 + d] + red[128 + d] + red[192 + d];
}

// in-place exclusive suffix of chunk sums
__global__ void scan_offsets() {
    int i = blockIdx.x * 256 + threadIdx.x;          // 2048 columns
    int bh = i >> 6, d = i & 63;
    float v[NCH];
    #pragma unroll
    for (int c = 0; c < NCH; ++c) v[c] = g_csum[(bh * NCH + c) * 64 + d];
    float run = 0.f;
    #pragma unroll
    for (int c = NCH - 1; c >= 0; --c) {
        g_csum[(bh * NCH + c) * 64 + d] = run;
        run += v[c];
    }
}

// ---------------- main attention kernel ----------------
#define QSCALE 0.18033688011112042f   // 0.125 * log2(e)
#define ONES2  0x3C003C00u            // two fp16 1.0
#define SM_FULL0  (NSTG * TILE_B)         // full[4]: tx barriers (+0,+8,+16,+24)
#define SM_EMPTY0 (NSTG * TILE_B + 32)    // empty[4]: 8 warp-arrival barriers
#define SM_TOTAL  (NSTG * TILE_B + 128)   // 65664 -> 2 CTAs/SM

extern __shared__ __align__(1024) char dynsm[];

// one s-tile: wait full -> QK MMAs -> V prefetch -> exp/pack -> den MMA -> PV MMAs -> arrive -> refill
template <bool MASKED>
__device__ __forceinline__ void tile_body(
    int t, int st, int rpar, int tmax_glob, uint32_t sm, const unsigned char* kvbase,
    const uint32_t Qh[4][4],
    float Oa[8][4], float Dden[4],
    int tid, int lane, int rowglob,
    int ks_row, uint32_t k_col, int vs_row, uint32_t v_col, uint32_t xo)
{
    MBAR_WAIT(sm + SM_FULL0 + st * 8, rpar);

    const uint32_t stg = sm + (uint32_t)st * TILE_B;
    const uint32_t k_b = stg, v_b = stg + 8192;

    // ---- S = Q Kt (single fp16) ----
    float S[8][4];
    #pragma unroll
    for (int i = 0; i < 8; ++i)
        #pragma unroll
        for (int j = 0; j < 4; ++j) S[i][j] = 0.f;

    #pragma unroll
    for (int kc = 0; kc < 4; ++kc) {
        #pragma unroll
        for (int nbp = 0; nbp < 4; ++nbp) {
            uint32_t off = (uint32_t)(nbp * 16 + ks_row) * 128
                         + (((uint32_t)kc * 32 + k_col) ^ xo);
            uint32_t kb[4];
            ldsm4(k_b + off, kb);
            mma16816h(S[2*nbp],   Qh[kc], kb[0], kb[1]);
            mma16816h(S[2*nbp+1], Qh[kc], kb[2], kb[3]);
        }
    }

    // ---- prefetch V for kcs=0 (overlaps the exp MUFU stretch) ----
    uint32_t vbuf[2][4][4];
    #pragma unroll
    for (int nbp = 0; nbp < 4; ++nbp) {
        uint32_t off = (uint32_t)(vs_row) * 128 + (((uint32_t)nbp * 32 + v_col) ^ xo);
        ldsm4t(v_b + off, vbuf[0][nbp]);
    }

    // ---- exp; masked (future) slots contribute exp(0)=1 (reference semantics) ----
    const int quad = lane & 3;
    const int lim0 = MASKED ? (rowglob - (t << 6)) : 0;
    const int lim1 = lim0 + 8;
    uint32_t Ph[4][4];
    #pragma unroll
    for (int nb = 0; nb < 8; ++nb) {
        float p0, p1, p2, p3;
        if (MASKED) {
            int s0 = nb * 8 + quad * 2;
            p0 = (s0     <= lim0) ? ex2f(S[nb][0]) : 1.f;
            p1 = (s0 + 1 <= lim0) ? ex2f(S[nb][1]) : 1.f;
            p2 = (s0     <= lim1) ? ex2f(S[nb][2]) : 1.f;
            p3 = (s0 + 1 <= lim1) ? ex2f(S[nb][3]) : 1.f;
        } else {
            p0 = ex2f(S[nb][0]);
            p1 = ex2f(S[nb][1]);
            p2 = ex2f(S[nb][2]);
            p3 = ex2f(S[nb][3]);
        }
        Ph[nb >> 1][(nb & 1) * 2]     = packf16(p0, p1);
        Ph[nb >> 1][(nb & 1) * 2 + 1] = packf16(p2, p3);
    }

    // ---- den += P * ones (row sums on tensor pipe; all quad lanes get same value) ----
    #pragma unroll
    for (int kcs = 0; kcs < 4; ++kcs)
        mma16816h(Dden, Ph[kcs], ONES2, ONES2);

    // ---- O += P V (rotated V buffers) ----
    #pragma unroll
    for (int kcs = 0; kcs < 4; ++kcs) {
        if (kcs < 3) {
            #pragma unroll
            for (int nbp = 0; nbp < 4; ++nbp) {
                uint32_t off = (uint32_t)((kcs + 1) * 16 + vs_row) * 128
                             + (((uint32_t)nbp * 32 + v_col) ^ xo);
                ldsm4t(v_b + off, vbuf[(kcs + 1) & 1][nbp]);
            }
        }
        #pragma unroll
        for (int nbp = 0; nbp < 4; ++nbp) {
            const uint32_t* vb = vbuf[kcs & 1][nbp];
            mma16816h(Oa[2*nbp],   Ph[kcs], vb[0], vb[1]);
            mma16816h(Oa[2*nbp+1], Ph[kcs], vb[2], vb[3]);
        }
    }

    // this warp is done reading stage st (MMA consumption guarantees ldsm completion)
    if (lane == 0) MBAR_ARRIVE(sm + SM_EMPTY0 + st * 8);

    // producer: refill stage once all 8 warps arrived
    if (tid == 0 && t + NSTG <= tmax_glob) {
        MBAR_WAIT(sm + SM_EMPTY0 + st * 8, rpar);
        MBAR_EXPECT_TX(sm + SM_FULL0 + st * 8, TILE_B);
        bulk_ld(stg, kvbase + (size_t)(t + NSTG) * TILE_B, TILE_B, sm + SM_FULL0 + st * 8);
    }
}

__global__ void __launch_bounds__(256, 2) attn_mma(const float* __restrict__ Q,
                                                   float* __restrict__ O) {
    const uint32_t sm = smem_u32(dynsm);
    const int tid = threadIdx.x;
    const int w = tid >> 5, lane = tid & 31;
    const int g = lane >> 2, quad = lane & 3;
    const int bh = blockIdx.y, b = bh >> 4, h = bh & 15;
    const int mtile = (NQT - 1) - (int)blockIdx.x;   // heavy q-tiles first
    const int tmax_glob = 2 * mtile + 1;             // max s-tile any warp needs
    // warps 0-3 (rows 0-63): the tile past the diagonal is ALL-masked (p=1) -> skip it
    const int nproc = 2 * mtile + 2 - (w < 4 ? 1 : 0);   // tiles processed; last one MASKED

    if (tid == 0) {
        #pragma unroll
        for (int s = 0; s < NSTG; ++s) {
            MBAR_INIT(sm + SM_FULL0 + s * 8, 1);
            MBAR_INIT(sm + SM_EMPTY0 + s * 8, 8);
        }
    }

    // per-lane ldmatrix geometry (XOR-swizzled, 128B rows)
    const int ks_row = (lane & 7) + ((lane >> 4) << 3);
    const uint32_t k_col = ((uint32_t)((lane >> 3) & 1)) * 16;
    const int vs_row = (lane & 7) + (((lane >> 3) & 1) << 3);
    const uint32_t v_col = ((uint32_t)(lane >> 4)) << 4;
    const uint32_t xo = ((uint32_t)(lane & 7)) << 4;

    // ---- Q fragments (single fp16, scale folded in) ----
    uint32_t Qh[4][4];
    {
        const float* qb = Q + (((size_t)b * Lc + (size_t)mtile * BM + w * 16) * Hc + h) * 64;
        #pragma unroll
        for (int kc = 0; kc < 4; ++kc) {
            int e0 = kc * 16 + quad * 2;
            float2 v00 = *(const float2*)(qb + (size_t)g * 1024 + e0);
            float2 v10 = *(const float2*)(qb + (size_t)(g + 8) * 1024 + e0);
            float2 v01 = *(const float2*)(qb + (size_t)g * 1024 + e0 + 8);
            float2 v11 = *(const float2*)(qb + (size_t)(g + 8) * 1024 + e0 + 8);
            Qh[kc][0] = packf16(v00.x * QSCALE, v00.y * QSCALE);
            Qh[kc][1] = packf16(v10.x * QSCALE, v10.y * QSCALE);
            Qh[kc][2] = packf16(v01.x * QSCALE, v01.y * QSCALE);
            Qh[kc][3] = packf16(v11.x * QSCALE, v11.y * QSCALE);
        }
    }
    __syncthreads();   // mbarrier init visible to all warps

    // prologue: fill the ring
    const unsigned char* kvbase = g_KV + (size_t)bh * NST * TILE_B;
    if (tid == 0) {
        #pragma unroll
        for (int s = 0; s < NSTG; ++s) {
            if (s <= tmax_glob) {
                MBAR_EXPECT_TX(sm + SM_FULL0 + s * 8, TILE_B);
                bulk_ld(sm + s * TILE_B, kvbase + (size_t)s * TILE_B, TILE_B,
                        sm + SM_FULL0 + s * 8);
            }
        }
    }

    float Oa[8][4];
    #pragma unroll
    for (int i = 0; i < 8; ++i)
        #pragma unroll
        for (int j = 0; j < 4; ++j) Oa[i][j] = 0.f;
    float Dden[4] = {0.f, 0.f, 0.f, 0.f};

    const int rowA = w * 16 + g;
    const int rowglob = mtile * BM + rowA;

    int t = 0, st = 0, rp = 0;
    #pragma unroll 1
    for (; t < nproc - 1; ++t) {
        tile_body<false>(t, st, rp, tmax_glob, sm, kvbase, Qh, Oa, Dden,
                         tid, lane, rowglob, ks_row, k_col, vs_row, v_col, xo);
        if (++st == NSTG) { st = 0; rp ^= 1; }
    }
    tile_body<true>(t, st, rp, tmax_glob, sm, kvbase, Qh, Oa, Dden,
                    tid, lane, rowglob, ks_row, k_col, vs_row, v_col, xo);

    // ---- epilogue ----
    // Dden[0]/Dden[2] hold full row sums (rows g, g+8) — no shuffle needed.
    const float corr = (float)(Lc - BN * nproc);   // masked slots beyond processed tiles
    const float inv0 = 1.f / (Dden[0] + corr);
    const float inv1 = 1.f / (Dden[2] + corr);

    const int r0g = rowglob;
    const int r1g = r0g + 8;
    const size_t ob0 = (((size_t)b * Lc + r0g) * Hc + h) * 64;
    const size_t ob1 = (((size_t)b * Lc + r1g) * Hc + h) * 64;
    const float* sfx = &g_csum[(bh * NCH + (nproc - 1)) * 64];  // V-sum over chunks >= nproc

    #pragma unroll
    for (int nb = 0; nb < 8; ++nb) {
        int d0 = nb * 8 + quad * 2;
        float2 s2 = *(const float2*)(sfx + d0);
        float2 o0 = make_float2((Oa[nb][0] + s2.x) * inv0, (Oa[nb][1] + s2.y) * inv0);
        float2 o1 = make_float2((Oa[nb][2] + s2.x) * inv1, (Oa[nb][3] + s2.y) * inv1);
        *(float2*)&O[ob0 + d0] = o0;
        *(float2*)&O[ob1 + d0] = o1;
    }
}

// ---------------- launch ----------------
extern "C" void kernel_launch(void* const* d_in, const int* in_sizes, int n_in,
                              void* d_out, int out_size) {
    const float* Q = (const float*)d_in[0];
    const float* K = (const float*)d_in[1];
    const float* V = (const float*)d_in[2];
    float* O = (float*)d_out;

    convert_kv<<<2048, 256>>>(K, V);
    scan_chunks<<<dim3(NCH, BHc), 256>>>(V);
    scan_offsets<<<8, 256>>>();

    cudaFuncSetAttribute(attn_mma, cudaFuncAttributeMaxDynamicSharedMemorySize, SM_TOTAL);
    attn_mma<<<dim3(NQT, BHc), 256, SM_TOTAL>>>(Q, O);
}